// round 1
// baseline (speedup 1.0000x reference)
#include <cuda_runtime.h>
#include <cuda_bf16.h>
#include <cstdint>
#include <cmath>

// Problem constants
#define TT 100
#define BB 1000
#define EE 512
#define DD 256
#define LL 4
#define MROWS (TT*BB)          // 100000

// ---------------- scratch (static device memory; no allocations) ----------------
__device__ float g_xl[(size_t)MROWS * EE];   // LN output / head hidden
__device__ float g_U [(size_t)MROWS * 2048]; // projected gates, both directions
__device__ float g_x [(size_t)MROWS * EE];   // layer activations (ping in place)

// ---------------- helpers ----------------
__device__ __forceinline__ uint32_t f2tf32(float x) {
    uint32_t r;
    asm("cvt.rna.tf32.f32 %0, %1;" : "=r"(r) : "f"(x));
    return r;
}

__device__ __forceinline__ void mma_tf32(float c[4], const uint32_t a[4], const uint32_t b[2]) {
    asm volatile(
        "mma.sync.aligned.m16n8k8.row.col.f32.tf32.tf32.f32 "
        "{%0,%1,%2,%3}, {%4,%5,%6,%7}, {%8,%9}, {%0,%1,%2,%3};\n"
        : "+f"(c[0]), "+f"(c[1]), "+f"(c[2]), "+f"(c[3])
        : "r"(a[0]), "r"(a[1]), "r"(a[2]), "r"(a[3]), "r"(b[0]), "r"(b[1]));
}

// ---------------- LayerNorm: one warp per token (E=512) ----------------
__global__ void __launch_bounds__(256) ln_kernel(
    const float* __restrict__ x, const float* __restrict__ g,
    const float* __restrict__ b, float* __restrict__ out, int Mrows)
{
    int warp = (blockIdx.x * blockDim.x + threadIdx.x) >> 5;
    int lane = threadIdx.x & 31;
    if (warp >= Mrows) return;

    const float4* xr = (const float4*)(x + (size_t)warp * EE);
    float4 v[4];
    float s = 0.f, sq = 0.f;
#pragma unroll
    for (int j = 0; j < 4; j++) {
        v[j] = xr[lane + j * 32];
        s  += v[j].x + v[j].y + v[j].z + v[j].w;
        sq += v[j].x*v[j].x + v[j].y*v[j].y + v[j].z*v[j].z + v[j].w*v[j].w;
    }
#pragma unroll
    for (int o = 16; o > 0; o >>= 1) {
        s  += __shfl_xor_sync(0xffffffffu, s, o);
        sq += __shfl_xor_sync(0xffffffffu, sq, o);
    }
    float mean = s * (1.f / EE);
    float var  = sq * (1.f / EE) - mean * mean;
    float rstd = rsqrtf(var + 1e-5f);

    float4* orow = (float4*)(out + (size_t)warp * EE);
    const float4* gg4 = (const float4*)g;
    const float4* bb4 = (const float4*)b;
#pragma unroll
    for (int j = 0; j < 4; j++) {
        int e4 = lane + j * 32;
        float4 gg = gg4[e4], bb = bb4[e4], w;
        w.x = (v[j].x - mean) * rstd * gg.x + bb.x;
        w.y = (v[j].y - mean) * rstd * gg.y + bb.y;
        w.z = (v[j].z - mean) * rstd * gg.z + bb.z;
        w.w = (v[j].w - mean) * rstd * gg.w + bb.w;
        orow[e4] = w;
    }
}

// ---------------- tf32 GEMM: C[M,N] = A[M,512] * B(512,N), 128x128x32 tiles ----------------
// B addressing: n -> d = n>>dlog2 (direction), col = n & mask; addr = Bmat + d*dstride + k*ldb + col
#define A_TILE (128*36)
#define B_TILE (32*132)
#define GEMM_SMEM ((2*A_TILE + 2*B_TILE) * 4)

__global__ void __launch_bounds__(256) gemm_tf32(
    const float* __restrict__ A, const float* __restrict__ Bmat,
    const float* __restrict__ bias, float* __restrict__ C,
    int Mrows, int Ncols, int ldb, int dlog2, long long dstride)
{
    extern __shared__ float sm[];
    float* As = sm;
    float* Bs = sm + 2 * A_TILE;

    const int tid  = threadIdx.x;
    const int warp = tid >> 5, lane = tid & 31;
    const int g = lane >> 2, t = lane & 3;
    const int wm0 = (warp >> 2) * 64;   // 2 warps along M
    const int wn0 = (warp & 3) * 32;    // 4 warps along N
    const int m0 = blockIdx.y * 128;
    const int n0 = blockIdx.x * 128;
    const int d  = n0 >> dlog2;
    const int ncb = n0 & ((1 << dlog2) - 1);
    const float* Bbase = Bmat + (size_t)d * dstride + ncb;

    float acc[4][4][4];
#pragma unroll
    for (int i = 0; i < 4; i++)
#pragma unroll
        for (int j = 0; j < 4; j++)
#pragma unroll
            for (int k = 0; k < 4; k++) acc[i][j][k] = 0.f;

    float4 a_st[4], b_st[4];

    // prologue: load k-tile 0
#pragma unroll
    for (int j = 0; j < 4; j++) {
        int lin = tid + j * 256;
        int ar = lin >> 3, ac4 = lin & 7;
        int m = m0 + ar;
        a_st[j] = (m < Mrows) ? *(const float4*)(A + (size_t)m * EE + ac4 * 4)
                              : make_float4(0.f, 0.f, 0.f, 0.f);
        int br = lin >> 5, bc4 = lin & 31;
        b_st[j] = *(const float4*)(Bbase + (size_t)br * ldb + bc4 * 4);
    }
#pragma unroll
    for (int j = 0; j < 4; j++) {
        int lin = tid + j * 256;
        int ar = lin >> 3, ac4 = lin & 7;
        float4 cv;
        cv.x = __uint_as_float(f2tf32(a_st[j].x));
        cv.y = __uint_as_float(f2tf32(a_st[j].y));
        cv.z = __uint_as_float(f2tf32(a_st[j].z));
        cv.w = __uint_as_float(f2tf32(a_st[j].w));
        *(float4*)(As + ar * 36 + ac4 * 4) = cv;
        int br = lin >> 5, bc4 = lin & 31;
        float4 cb;
        cb.x = __uint_as_float(f2tf32(b_st[j].x));
        cb.y = __uint_as_float(f2tf32(b_st[j].y));
        cb.z = __uint_as_float(f2tf32(b_st[j].z));
        cb.w = __uint_as_float(f2tf32(b_st[j].w));
        *(float4*)(Bs + br * 132 + bc4 * 4) = cb;
    }
    __syncthreads();

    const int NKT = EE / 32;  // 16
    for (int kt = 0; kt < NKT; kt++) {
        int cur = kt & 1;
        if (kt < NKT - 1) {
            int k0 = (kt + 1) * 32;
#pragma unroll
            for (int j = 0; j < 4; j++) {
                int lin = tid + j * 256;
                int ar = lin >> 3, ac4 = lin & 7;
                int m = m0 + ar;
                a_st[j] = (m < Mrows) ? *(const float4*)(A + (size_t)m * EE + k0 + ac4 * 4)
                                      : make_float4(0.f, 0.f, 0.f, 0.f);
                int br = lin >> 5, bc4 = lin & 31;
                b_st[j] = *(const float4*)(Bbase + (size_t)(k0 + br) * ldb + bc4 * 4);
            }
        }
        const float* Ac = As + cur * A_TILE;
        const float* Bc = Bs + cur * B_TILE;
#pragma unroll
        for (int ks = 0; ks < 4; ks++) {
            int kk = ks * 8;
            uint32_t af[4][4], bf[4][2];
#pragma unroll
            for (int i = 0; i < 4; i++) {
                int r = wm0 + i * 16 + g;
                af[i][0] = __float_as_uint(Ac[(r)     * 36 + kk + t]);
                af[i][1] = __float_as_uint(Ac[(r + 8) * 36 + kk + t]);
                af[i][2] = __float_as_uint(Ac[(r)     * 36 + kk + t + 4]);
                af[i][3] = __float_as_uint(Ac[(r + 8) * 36 + kk + t + 4]);
            }
#pragma unroll
            for (int j = 0; j < 4; j++) {
                int cn = wn0 + j * 8 + g;
                bf[j][0] = __float_as_uint(Bc[(kk + t)     * 132 + cn]);
                bf[j][1] = __float_as_uint(Bc[(kk + t + 4) * 132 + cn]);
            }
#pragma unroll
            for (int i = 0; i < 4; i++)
#pragma unroll
                for (int j = 0; j < 4; j++)
                    mma_tf32(acc[i][j], af[i], bf[j]);
        }
        if (kt < NKT - 1) {
            int nb = (kt + 1) & 1;
            float* Ad = As + nb * A_TILE;
            float* Bd = Bs + nb * B_TILE;
#pragma unroll
            for (int j = 0; j < 4; j++) {
                int lin = tid + j * 256;
                int ar = lin >> 3, ac4 = lin & 7;
                float4 cv;
                cv.x = __uint_as_float(f2tf32(a_st[j].x));
                cv.y = __uint_as_float(f2tf32(a_st[j].y));
                cv.z = __uint_as_float(f2tf32(a_st[j].z));
                cv.w = __uint_as_float(f2tf32(a_st[j].w));
                *(float4*)(Ad + ar * 36 + ac4 * 4) = cv;
                int br = lin >> 5, bc4 = lin & 31;
                float4 cb;
                cb.x = __uint_as_float(f2tf32(b_st[j].x));
                cb.y = __uint_as_float(f2tf32(b_st[j].y));
                cb.z = __uint_as_float(f2tf32(b_st[j].z));
                cb.w = __uint_as_float(f2tf32(b_st[j].w));
                *(float4*)(Bd + br * 132 + bc4 * 4) = cb;
            }
        }
        __syncthreads();
    }

    // epilogue
#pragma unroll
    for (int i = 0; i < 4; i++) {
        int r0 = m0 + wm0 + i * 16 + g;
        int r1 = r0 + 8;
#pragma unroll
        for (int j = 0; j < 4; j++) {
            int c = n0 + wn0 + j * 8 + 2 * t;
            float b0v = 0.f, b1v = 0.f;
            if (bias) { b0v = bias[c]; b1v = bias[c + 1]; }
            if (r0 < Mrows) {
                float2 o = make_float2(acc[i][j][0] + b0v, acc[i][j][1] + b1v);
                *(float2*)(C + (size_t)r0 * Ncols + c) = o;
            }
            if (r1 < Mrows) {
                float2 o = make_float2(acc[i][j][2] + b0v, acc[i][j][3] + b1v);
                *(float2*)(C + (size_t)r1 * Ncols + c) = o;
            }
        }
    }
}

// ---------------- SRU elementwise scan, both directions; one thread per (dir,b,d) lane ----------------
__global__ void __launch_bounds__(256) sru_scan(
    const float* __restrict__ U, const float* __restrict__ v,
    const float* __restrict__ bp, float* __restrict__ X)
{
    int tid = blockIdx.x * blockDim.x + threadIdx.x;
    if (tid >= 2 * BB * DD) return;
    int dir = tid / (BB * DD);
    int rem = tid - dir * (BB * DD);
    int b = rem / DD;
    int dd = rem - b * DD;

    float vf = v[dir * 2 * DD + dd];
    float vr = v[dir * 2 * DD + DD + dd];
    float bf = bp[dir * 2 * DD + dd];
    float br = bp[dir * 2 * DD + DD + dd];

    const size_t colU = (size_t)dir * 1024 + dd;
    const size_t colX = (size_t)dir * DD + dd;

    float c = 0.f;
    for (int s = 0; s < TT; s++) {
        int t = dir ? (TT - 1 - s) : s;
        const float* up = U + ((size_t)t * BB + b) * 2048 + colU;
        float u0 = up[0], u1 = up[256], u2 = up[512], u3 = up[768];
        float f = 1.f / (1.f + expf(-(u1 + vf * c + bf)));
        c = f * c + (1.f - f) * u0;
        float r = 1.f / (1.f + expf(-(u2 + vr * c + br)));
        X[((size_t)t * BB + b) * EE + colX] = r * c + (1.f - r) * u3;
    }
}

// ---------------- head: BN(eval) + relu + W2 (512x4) + log_softmax; one warp per token ----------------
__global__ void __launch_bounds__(256) head_kernel(
    const float* __restrict__ h,
    const float* __restrict__ bn_g, const float* __restrict__ bn_b,
    const float* __restrict__ bn_mean, const float* __restrict__ bn_var,
    const float* __restrict__ W2, const float* __restrict__ b2,
    float* __restrict__ out, int Mrows)
{
    __shared__ float w2s[EE * 4];
    __shared__ float scs[EE], tbs[EE];
    __shared__ float b2s[4];
    int tid = threadIdx.x;
    for (int i = tid; i < EE * 4; i += 256) w2s[i] = W2[i];
    for (int i = tid; i < EE; i += 256) {
        float s = bn_g[i] * rsqrtf(bn_var[i] + 1e-5f);
        scs[i] = s;
        tbs[i] = bn_b[i] - bn_mean[i] * s;
    }
    if (tid < 4) b2s[tid] = b2[tid];
    __syncthreads();

    int warp = (blockIdx.x * blockDim.x + tid) >> 5;
    int lane = tid & 31;
    if (warp >= Mrows) return;

    const float4* hr = (const float4*)(h + (size_t)warp * EE);
    float a0 = 0.f, a1 = 0.f, a2 = 0.f, a3 = 0.f;
#pragma unroll
    for (int j = 0; j < 4; j++) {
        int e4 = lane + j * 32;
        float4 hv = hr[e4];
        int e = e4 * 4;
        float vals[4] = {hv.x, hv.y, hv.z, hv.w};
#pragma unroll
        for (int k = 0; k < 4; k++) {
            float val = fmaxf(vals[k] * scs[e + k] + tbs[e + k], 0.f);
            a0 += val * w2s[(e + k) * 4 + 0];
            a1 += val * w2s[(e + k) * 4 + 1];
            a2 += val * w2s[(e + k) * 4 + 2];
            a3 += val * w2s[(e + k) * 4 + 3];
        }
    }
#pragma unroll
    for (int o = 16; o > 0; o >>= 1) {
        a0 += __shfl_xor_sync(0xffffffffu, a0, o);
        a1 += __shfl_xor_sync(0xffffffffu, a1, o);
        a2 += __shfl_xor_sync(0xffffffffu, a2, o);
        a3 += __shfl_xor_sync(0xffffffffu, a3, o);
    }
    if (lane == 0) {
        float l0 = a0 + b2s[0], l1 = a1 + b2s[1], l2 = a2 + b2s[2], l3 = a3 + b2s[3];
        float m = fmaxf(fmaxf(l0, l1), fmaxf(l2, l3));
        float se = expf(l0 - m) + expf(l1 - m) + expf(l2 - m) + expf(l3 - m);
        float lse = m + logf(se);
        float4 o = make_float4(l0 - lse, l1 - lse, l2 - lse, l3 - lse);
        ((float4*)out)[warp] = o;
    }
}

// ---------------- launch ----------------
extern "C" void kernel_launch(void* const* d_in, const int* in_sizes, int n_in,
                              void* d_out, int out_size)
{
    const float* sentence = (const float*)d_in[0];
    const float* sru_W    = (const float*)d_in[1];
    const float* sru_v    = (const float*)d_in[2];
    const float* sru_b    = (const float*)d_in[3];
    const float* ln_g     = (const float*)d_in[4];
    const float* ln_b     = (const float*)d_in[5];
    const float* W1       = (const float*)d_in[6];
    const float* b1       = (const float*)d_in[7];
    const float* bn_g     = (const float*)d_in[8];
    const float* bn_b     = (const float*)d_in[9];
    const float* bn_mean  = (const float*)d_in[10];
    const float* bn_var   = (const float*)d_in[11];
    const float* W2       = (const float*)d_in[12];
    const float* b2       = (const float*)d_in[13];
    float* out = (float*)d_out;

    float *xl, *U, *x;
    cudaGetSymbolAddress((void**)&xl, g_xl);
    cudaGetSymbolAddress((void**)&U,  g_U);
    cudaGetSymbolAddress((void**)&x,  g_x);

    cudaFuncSetAttribute(gemm_tf32, cudaFuncAttributeMaxDynamicSharedMemorySize, GEMM_SMEM);

    const int M = MROWS;
    const int mtiles = (M + 127) / 128;  // 782
    dim3 gemm_grid_layer(2048 / 128, mtiles);
    dim3 gemm_grid_head(EE / 128, mtiles);
    int ln_blocks = (M * 32 + 255) / 256;       // 12500
    int scan_blocks = (2 * BB * DD + 255) / 256; // 2000

    for (int l = 0; l < LL; l++) {
        const float* xin = (l == 0) ? sentence : x;
        ln_kernel<<<ln_blocks, 256>>>(xin, ln_g + l * EE, ln_b + l * EE, xl, M);
        gemm_tf32<<<gemm_grid_layer, 256, GEMM_SMEM>>>(
            xl, sru_W + (size_t)l * 2 * EE * 1024, nullptr, U,
            M, 2048, 1024, 10, (long long)EE * 1024);
        sru_scan<<<scan_blocks, 256>>>(U, sru_v + l * 4 * DD, sru_b + l * 4 * DD, x);
    }
    // head GEMM: h = x @ W1 + b1 -> xl
    gemm_tf32<<<gemm_grid_head, 256, GEMM_SMEM>>>(
        x, W1, b1, xl, M, EE, EE, 30, 0LL);
    head_kernel<<<ln_blocks, 256>>>(xl, bn_g, bn_b, bn_mean, bn_var, W2, b2, out, M);
}

// round 5
// speedup vs baseline: 1.2904x; 1.2904x over previous
#include <cuda_runtime.h>
#include <cuda_bf16.h>
#include <cstdint>
#include <cmath>

// Problem constants
#define TT 100
#define BB 1000
#define EE 512
#define DD 256
#define LL 4
#define MROWS (TT*BB)          // 100000

// ---------------- scratch (static device memory; no allocations) ----------------
__device__ float g_xl[(size_t)MROWS * EE];    // LN output / head hidden
__device__ float g_U [(size_t)MROWS * 2048];  // projected gates, both directions
__device__ float g_x [(size_t)MROWS * EE];    // layer activations
__device__ float g_Wr [(size_t)LL * 2 * EE * 1024]; // tf32-rounded sru_W
__device__ float g_W1r[(size_t)EE * EE];            // tf32-rounded W1

// ---------------- helpers ----------------
__device__ __forceinline__ float rtf32(float x) {
    uint32_t r;
    asm("cvt.rna.tf32.f32 %0, %1;" : "=r"(r) : "f"(x));
    return __uint_as_float(r);
}

__device__ __forceinline__ void mma_tf32(float c[4], const uint32_t a[4], const uint32_t b[2]) {
    asm volatile(
        "mma.sync.aligned.m16n8k8.row.col.f32.tf32.tf32.f32 "
        "{%0,%1,%2,%3}, {%4,%5,%6,%7}, {%8,%9}, {%0,%1,%2,%3};\n"
        : "+f"(c[0]), "+f"(c[1]), "+f"(c[2]), "+f"(c[3])
        : "r"(a[0]), "r"(a[1]), "r"(a[2]), "r"(a[3]), "r"(b[0]), "r"(b[1]));
}

// ---------------- pre-round weights to tf32 (grid-stride) ----------------
__global__ void __launch_bounds__(256) round_kernel(
    const float* __restrict__ in, float* __restrict__ out, int n)
{
    for (int i = blockIdx.x * blockDim.x + threadIdx.x; i < n; i += gridDim.x * blockDim.x)
        out[i] = rtf32(in[i]);
}

// ---------------- LayerNorm: one warp per token (E=512); tf32-rounded output ----------------
__global__ void __launch_bounds__(256) ln_kernel(
    const float* __restrict__ x, const float* __restrict__ g,
    const float* __restrict__ b, float* __restrict__ out, int Mrows)
{
    int warp = (blockIdx.x * blockDim.x + threadIdx.x) >> 5;
    int lane = threadIdx.x & 31;
    if (warp >= Mrows) return;

    const float4* xr = (const float4*)(x + (size_t)warp * EE);
    float4 v[4];
    float s = 0.f, sq = 0.f;
#pragma unroll
    for (int j = 0; j < 4; j++) {
        v[j] = xr[lane + j * 32];
        s  += v[j].x + v[j].y + v[j].z + v[j].w;
        sq += v[j].x*v[j].x + v[j].y*v[j].y + v[j].z*v[j].z + v[j].w*v[j].w;
    }
#pragma unroll
    for (int o = 16; o > 0; o >>= 1) {
        s  += __shfl_xor_sync(0xffffffffu, s, o);
        sq += __shfl_xor_sync(0xffffffffu, sq, o);
    }
    float mean = s * (1.f / EE);
    float var  = sq * (1.f / EE) - mean * mean;
    float rstd = rsqrtf(var + 1e-5f);

    float4* orow = (float4*)(out + (size_t)warp * EE);
    const float4* gg4 = (const float4*)g;
    const float4* bb4 = (const float4*)b;
#pragma unroll
    for (int j = 0; j < 4; j++) {
        int e4 = lane + j * 32;
        float4 gg = gg4[e4], bb = bb4[e4], w;
        w.x = rtf32((v[j].x - mean) * rstd * gg.x + bb.x);
        w.y = rtf32((v[j].y - mean) * rstd * gg.y + bb.y);
        w.z = rtf32((v[j].z - mean) * rstd * gg.z + bb.z);
        w.w = rtf32((v[j].w - mean) * rstd * gg.w + bb.w);
        orow[e4] = w;
    }
}

// ---------------- tf32 GEMM v2: cp.async 3-stage, 128x256x32 tiles ----------------
#define BM 128
#define BN 256
#define BK 32
#define LDA 36
#define LDB 260
#define A_ST (BM*LDA)          // 4608 floats
#define B_ST (BK*LDB)          // 8320 floats
#define STAGE_F (A_ST + B_ST)  // 12928 floats
#define GEMM_SMEM (3*STAGE_F*4)  // 155136 bytes

__device__ __forceinline__ void cp16(uint32_t dst, const float* src, int sz) {
    asm volatile("cp.async.ca.shared.global [%0], [%1], 16, %2;" :: "r"(dst), "l"(src), "r"(sz));
}

__global__ void __launch_bounds__(256, 1) gemm_tf32(
    const float* __restrict__ A, const float* __restrict__ Bmat,
    const float* __restrict__ bias, float* __restrict__ C,
    int Mrows, int Ncols, int ldb, int dlog2, long long dstride)
{
    extern __shared__ float sm[];
    const int tid  = threadIdx.x;
    const int warp = tid >> 5, lane = tid & 31;
    const int g = lane >> 2, t = lane & 3;
    const int wm0 = (warp >> 2) * 64;   // 2 warps along M
    const int wn0 = (warp & 3) * 64;    // 4 warps along N
    const int m0 = blockIdx.y * BM;
    const int n0 = blockIdx.x * BN;
    const int d  = n0 >> dlog2;
    const int ncb = n0 & ((1 << dlog2) - 1);
    const float* Bbase = Bmat + (size_t)d * dstride + ncb;

    // per-thread cp.async coordinates
    const int a_row = tid >> 3;            // 0..31, +s*32
    const int a_c4  = (tid & 7) * 4;       // float offset within row
    const int b_row = tid >> 6;            // 0..3, +s*4
    const int b_c4  = (tid & 63) * 4;

    float acc[4][8][4];
#pragma unroll
    for (int i = 0; i < 4; i++)
#pragma unroll
        for (int j = 0; j < 8; j++)
#pragma unroll
            for (int k = 0; k < 4; k++) acc[i][j][k] = 0.f;

    auto issue = [&](int kt, int buf) {
        float* As = sm + buf * STAGE_F;
        float* Bs = As + A_ST;
        const int k0 = kt * BK;
#pragma unroll
        for (int s = 0; s < 4; s++) {
            int row = a_row + s * 32;
            int m = m0 + row;
            uint32_t dst = (uint32_t)__cvta_generic_to_shared(As + row * LDA + a_c4);
            const float* src = A + (size_t)m * EE + k0 + a_c4;
            cp16(dst, src, (m < Mrows) ? 16 : 0);
        }
#pragma unroll
        for (int s = 0; s < 8; s++) {
            int row = b_row + s * 4;
            uint32_t dst = (uint32_t)__cvta_generic_to_shared(Bs + row * LDB + b_c4);
            const float* src = Bbase + (size_t)(k0 + row) * ldb + b_c4;
            cp16(dst, src, 16);
        }
    };

    auto compute = [&](int buf) {
        const float* As = sm + buf * STAGE_F;
        const float* Bs = As + A_ST;
#pragma unroll
        for (int ks = 0; ks < 4; ks++) {
            const int kk = ks * 8;
            uint32_t af[4][4], bf[8][2];
#pragma unroll
            for (int i = 0; i < 4; i++) {
                int r = wm0 + i * 16 + g;
                af[i][0] = __float_as_uint(As[(r)     * LDA + kk + t]);
                af[i][1] = __float_as_uint(As[(r + 8) * LDA + kk + t]);
                af[i][2] = __float_as_uint(As[(r)     * LDA + kk + t + 4]);
                af[i][3] = __float_as_uint(As[(r + 8) * LDA + kk + t + 4]);
            }
#pragma unroll
            for (int j = 0; j < 8; j++) {
                int cn = wn0 + j * 8 + g;
                bf[j][0] = __float_as_uint(Bs[(kk + t)     * LDB + cn]);
                bf[j][1] = __float_as_uint(Bs[(kk + t + 4) * LDB + cn]);
            }
#pragma unroll
            for (int i = 0; i < 4; i++)
#pragma unroll
                for (int j = 0; j < 8; j++)
                    mma_tf32(acc[i][j], af[i], bf[j]);
        }
    };

    const int NKT = EE / BK;  // 16

    issue(0, 0);
    asm volatile("cp.async.commit_group;");
    issue(1, 1);
    asm volatile("cp.async.commit_group;");

    for (int kt = 0; kt < NKT; kt++) {
        if (kt + 2 < NKT) issue(kt + 2, (kt + 2) % 3);
        asm volatile("cp.async.commit_group;");
        asm volatile("cp.async.wait_group 2;");
        __syncthreads();
        compute(kt % 3);
        __syncthreads();
    }

    // epilogue
#pragma unroll
    for (int i = 0; i < 4; i++) {
        int r0 = m0 + wm0 + i * 16 + g;
        int r1 = r0 + 8;
#pragma unroll
        for (int j = 0; j < 8; j++) {
            int c = n0 + wn0 + j * 8 + 2 * t;
            float b0v = 0.f, b1v = 0.f;
            if (bias) { b0v = bias[c]; b1v = bias[c + 1]; }
            if (r0 < Mrows) {
                float2 o = make_float2(acc[i][j][0] + b0v, acc[i][j][1] + b1v);
                *(float2*)(C + (size_t)r0 * Ncols + c) = o;
            }
            if (r1 < Mrows) {
                float2 o = make_float2(acc[i][j][2] + b0v, acc[i][j][3] + b1v);
                *(float2*)(C + (size_t)r1 * Ncols + c) = o;
            }
        }
    }
}

// ---------------- SRU elementwise scan; tf32-rounded output ----------------
__global__ void __launch_bounds__(256) sru_scan(
    const float* __restrict__ U, const float* __restrict__ v,
    const float* __restrict__ bp, float* __restrict__ X)
{
    int tid = blockIdx.x * blockDim.x + threadIdx.x;
    if (tid >= 2 * BB * DD) return;
    int dir = tid / (BB * DD);
    int rem = tid - dir * (BB * DD);
    int b = rem / DD;
    int dd = rem - b * DD;

    float vf = v[dir * 2 * DD + dd];
    float vr = v[dir * 2 * DD + DD + dd];
    float bf = bp[dir * 2 * DD + dd];
    float br = bp[dir * 2 * DD + DD + dd];

    const size_t colU = (size_t)dir * 1024 + dd;
    const size_t colX = (size_t)dir * DD + dd;

    float c = 0.f;
    for (int s = 0; s < TT; s++) {
        int t = dir ? (TT - 1 - s) : s;
        const float* up = U + ((size_t)t * BB + b) * 2048 + colU;
        float u0 = up[0], u1 = up[256], u2 = up[512], u3 = up[768];
        float f = 1.f / (1.f + expf(-(u1 + vf * c + bf)));
        c = f * c + (1.f - f) * u0;
        float r = 1.f / (1.f + expf(-(u2 + vr * c + br)));
        X[((size_t)t * BB + b) * EE + colX] = rtf32(r * c + (1.f - r) * u3);
    }
}

// ---------------- head: BN(eval) + relu + W2 (512x4) + log_softmax; one warp per token ----------------
__global__ void __launch_bounds__(256) head_kernel(
    const float* __restrict__ h,
    const float* __restrict__ bn_g, const float* __restrict__ bn_b,
    const float* __restrict__ bn_mean, const float* __restrict__ bn_var,
    const float* __restrict__ W2, const float* __restrict__ b2,
    float* __restrict__ out, int Mrows)
{
    __shared__ float w2s[EE * 4];
    __shared__ float scs[EE], tbs[EE];
    __shared__ float b2s[4];
    int tid = threadIdx.x;
    for (int i = tid; i < EE * 4; i += 256) w2s[i] = W2[i];
    for (int i = tid; i < EE; i += 256) {
        float s = bn_g[i] * rsqrtf(bn_var[i] + 1e-5f);
        scs[i] = s;
        tbs[i] = bn_b[i] - bn_mean[i] * s;
    }
    if (tid < 4) b2s[tid] = b2[tid];
    __syncthreads();

    int warp = (blockIdx.x * blockDim.x + tid) >> 5;
    int lane = tid & 31;
    if (warp >= Mrows) return;

    const float4* hr = (const float4*)(h + (size_t)warp * EE);
    float a0 = 0.f, a1 = 0.f, a2 = 0.f, a3 = 0.f;
#pragma unroll
    for (int j = 0; j < 4; j++) {
        int e4 = lane + j * 32;
        float4 hv = hr[e4];
        int e = e4 * 4;
        float vals[4] = {hv.x, hv.y, hv.z, hv.w};
#pragma unroll
        for (int k = 0; k < 4; k++) {
            float val = fmaxf(vals[k] * scs[e + k] + tbs[e + k], 0.f);
            a0 += val * w2s[(e + k) * 4 + 0];
            a1 += val * w2s[(e + k) * 4 + 1];
            a2 += val * w2s[(e + k) * 4 + 2];
            a3 += val * w2s[(e + k) * 4 + 3];
        }
    }
#pragma unroll
    for (int o = 16; o > 0; o >>= 1) {
        a0 += __shfl_xor_sync(0xffffffffu, a0, o);
        a1 += __shfl_xor_sync(0xffffffffu, a1, o);
        a2 += __shfl_xor_sync(0xffffffffu, a2, o);
        a3 += __shfl_xor_sync(0xffffffffu, a3, o);
    }
    if (lane == 0) {
        float l0 = a0 + b2s[0], l1 = a1 + b2s[1], l2 = a2 + b2s[2], l3 = a3 + b2s[3];
        float m = fmaxf(fmaxf(l0, l1), fmaxf(l2, l3));
        float se = expf(l0 - m) + expf(l1 - m) + expf(l2 - m) + expf(l3 - m);
        float lse = m + logf(se);
        float4 o = make_float4(l0 - lse, l1 - lse, l2 - lse, l3 - lse);
        ((float4*)out)[warp] = o;
    }
}

// ---------------- launch ----------------
extern "C" void kernel_launch(void* const* d_in, const int* in_sizes, int n_in,
                              void* d_out, int out_size)
{
    const float* sentence = (const float*)d_in[0];
    const float* sru_W    = (const float*)d_in[1];
    const float* sru_v    = (const float*)d_in[2];
    const float* sru_b    = (const float*)d_in[3];
    const float* ln_g     = (const float*)d_in[4];
    const float* ln_b     = (const float*)d_in[5];
    const float* W1       = (const float*)d_in[6];
    const float* b1       = (const float*)d_in[7];
    const float* bn_g     = (const float*)d_in[8];
    const float* bn_b     = (const float*)d_in[9];
    const float* bn_mean  = (const float*)d_in[10];
    const float* bn_var   = (const float*)d_in[11];
    const float* W2       = (const float*)d_in[12];
    const float* b2       = (const float*)d_in[13];
    float* out = (float*)d_out;

    float *xl, *U, *x, *Wr, *W1r;
    cudaGetSymbolAddress((void**)&xl,  g_xl);
    cudaGetSymbolAddress((void**)&U,   g_U);
    cudaGetSymbolAddress((void**)&x,   g_x);
    cudaGetSymbolAddress((void**)&Wr,  g_Wr);
    cudaGetSymbolAddress((void**)&W1r, g_W1r);

    cudaFuncSetAttribute(gemm_tf32, cudaFuncAttributeMaxDynamicSharedMemorySize, GEMM_SMEM);

    const int M = MROWS;
    const int mtiles = (M + BM - 1) / BM;        // 782
    dim3 gemm_grid_layer(2048 / BN, mtiles);     // (8, 782)
    dim3 gemm_grid_head(EE / BN, mtiles);        // (2, 782)
    int ln_blocks = (M * 32 + 255) / 256;        // 12500
    int scan_blocks = (2 * BB * DD + 255) / 256; // 2000

    // pre-round weights once per launch
    round_kernel<<<1024, 256>>>(sru_W, Wr, LL * 2 * EE * 1024);
    round_kernel<<<256, 256>>>(W1, W1r, EE * EE);

    for (int l = 0; l < LL; l++) {
        const float* xin = (l == 0) ? sentence : x;
        ln_kernel<<<ln_blocks, 256>>>(xin, ln_g + l * EE, ln_b + l * EE, xl, M);
        gemm_tf32<<<gemm_grid_layer, 256, GEMM_SMEM>>>(
            xl, Wr + (size_t)l * 2 * EE * 1024, nullptr, U,
            M, 2048, 1024, 10, (long long)EE * 1024);
        sru_scan<<<scan_blocks, 256>>>(U, sru_v + l * 4 * DD, sru_b + l * 4 * DD, x);
    }
    // head GEMM: h = x @ W1 + b1 -> xl
    gemm_tf32<<<gemm_grid_head, 256, GEMM_SMEM>>>(
        x, W1r, b1, xl, M, EE, EE, 30, 0LL);
    head_kernel<<<ln_blocks, 256>>>(xl, bn_g, bn_b, bn_mean, bn_var, W2, b2, out, M);
}

// round 7
// speedup vs baseline: 1.8996x; 1.4722x over previous
#include <cuda_runtime.h>
#include <cuda_fp16.h>
#include <cstdint>
#include <cmath>

// Problem constants
#define TT 100
#define BB 1000
#define EE 512
#define DD 256
#define LL 4
#define MROWS (TT*BB)          // 100000

// ---------------- scratch (static device memory; no allocations) ----------------
__device__ __half g_xl[(size_t)MROWS * EE];    // LN output / head hidden (fp16)
__device__ __half g_U [(size_t)MROWS * 2048];  // projected gates (fp16)
__device__ __half g_x [(size_t)MROWS * EE];    // layer activations (fp16)
__device__ __half g_Wr [(size_t)LL * 2 * 1024 * EE]; // transposed+rounded sru_W: [l,d][n,k]
__device__ __half g_W1r[(size_t)EE * EE];            // transposed+rounded W1: [n,k]

// ---------------- helpers ----------------
__device__ __forceinline__ uint32_t su32(const void* p) {
    return (uint32_t)__cvta_generic_to_shared(p);
}

__device__ __forceinline__ void cp16(uint32_t dst, const void* src, int sz) {
    asm volatile("cp.async.ca.shared.global [%0], [%1], 16, %2;" :: "r"(dst), "l"(src), "r"(sz));
}

__device__ __forceinline__ void mma_f16(float c[4], const uint32_t a[4], const uint32_t b[2]) {
    asm volatile(
        "mma.sync.aligned.m16n8k16.row.col.f32.f16.f16.f32 "
        "{%0,%1,%2,%3}, {%4,%5,%6,%7}, {%8,%9}, {%0,%1,%2,%3};\n"
        : "+f"(c[0]), "+f"(c[1]), "+f"(c[2]), "+f"(c[3])
        : "r"(a[0]), "r"(a[1]), "r"(a[2]), "r"(a[3]), "r"(b[0]), "r"(b[1]));
}

// ---------------- transpose + fp16 round: [K,N] -> [N,K] per batch ----------------
__global__ void __launch_bounds__(256) transpose_half(
    const float* __restrict__ in, __half* __restrict__ out, int K, int N)
{
    __shared__ float tile[32][33];
    int b = blockIdx.z;
    const float* ip = in + (size_t)b * K * N;
    __half* op = out + (size_t)b * K * N;
    int k0 = blockIdx.y * 32, n0 = blockIdx.x * 32;
    int tx = threadIdx.x & 31, ty = threadIdx.x >> 5;  // 32x8
#pragma unroll
    for (int i = 0; i < 32; i += 8)
        tile[ty + i][tx] = ip[(size_t)(k0 + ty + i) * N + n0 + tx];
    __syncthreads();
#pragma unroll
    for (int i = 0; i < 32; i += 8)
        op[(size_t)(n0 + ty + i) * K + k0 + tx] = __float2half_rn(tile[tx][ty + i]);
}

// ---------------- LayerNorm (fp32 input, fp16 output): one warp per token ----------------
__global__ void __launch_bounds__(256) ln_f32(
    const float* __restrict__ x, const float* __restrict__ g,
    const float* __restrict__ b, __half* __restrict__ out, int Mrows)
{
    int warp = (blockIdx.x * blockDim.x + threadIdx.x) >> 5;
    int lane = threadIdx.x & 31;
    if (warp >= Mrows) return;

    const float4* xr = (const float4*)(x + (size_t)warp * EE);
    float4 v[4];
    float s = 0.f, sq = 0.f;
#pragma unroll
    for (int j = 0; j < 4; j++) {
        v[j] = xr[lane + j * 32];
        s  += v[j].x + v[j].y + v[j].z + v[j].w;
        sq += v[j].x*v[j].x + v[j].y*v[j].y + v[j].z*v[j].z + v[j].w*v[j].w;
    }
#pragma unroll
    for (int o = 16; o > 0; o >>= 1) {
        s  += __shfl_xor_sync(0xffffffffu, s, o);
        sq += __shfl_xor_sync(0xffffffffu, sq, o);
    }
    float mean = s * (1.f / EE);
    float var  = sq * (1.f / EE) - mean * mean;
    float rstd = rsqrtf(var + 1e-5f);

    __half2* orow = (__half2*)(out + (size_t)warp * EE);
    const float4* gg4 = (const float4*)g;
    const float4* bb4 = (const float4*)b;
#pragma unroll
    for (int j = 0; j < 4; j++) {
        int e4 = lane + j * 32;
        float4 gg = gg4[e4], bb = bb4[e4];
        float w0 = (v[j].x - mean) * rstd * gg.x + bb.x;
        float w1 = (v[j].y - mean) * rstd * gg.y + bb.y;
        float w2 = (v[j].z - mean) * rstd * gg.z + bb.z;
        float w3 = (v[j].w - mean) * rstd * gg.w + bb.w;
        orow[e4 * 2 + 0] = __floats2half2_rn(w0, w1);
        orow[e4 * 2 + 1] = __floats2half2_rn(w2, w3);
    }
}

// ---------------- LayerNorm (fp16 input, fp16 output) ----------------
__global__ void __launch_bounds__(256) ln_f16(
    const __half* __restrict__ x, const float* __restrict__ g,
    const float* __restrict__ b, __half* __restrict__ out, int Mrows)
{
    int warp = (blockIdx.x * blockDim.x + threadIdx.x) >> 5;
    int lane = threadIdx.x & 31;
    if (warp >= Mrows) return;

    const uint4* xr = (const uint4*)(x + (size_t)warp * EE);  // 8 halves per uint4
    uint4 v[2];
    float f[16];
    float s = 0.f, sq = 0.f;
#pragma unroll
    for (int j = 0; j < 2; j++) {
        v[j] = xr[lane + j * 32];
        const __half2* h2 = (const __half2*)&v[j];
#pragma unroll
        for (int q = 0; q < 4; q++) {
            float2 p = __half22float2(h2[q]);
            f[j * 8 + q * 2 + 0] = p.x;
            f[j * 8 + q * 2 + 1] = p.y;
            s += p.x + p.y;
            sq += p.x * p.x + p.y * p.y;
        }
    }
#pragma unroll
    for (int o = 16; o > 0; o >>= 1) {
        s  += __shfl_xor_sync(0xffffffffu, s, o);
        sq += __shfl_xor_sync(0xffffffffu, sq, o);
    }
    float mean = s * (1.f / EE);
    float var  = sq * (1.f / EE) - mean * mean;
    float rstd = rsqrtf(var + 1e-5f);

    uint4* orow = (uint4*)(out + (size_t)warp * EE);
#pragma unroll
    for (int j = 0; j < 2; j++) {
        int e0 = (lane + j * 32) * 8;
        uint4 w;
        __half2* wh = (__half2*)&w;
#pragma unroll
        for (int q = 0; q < 4; q++) {
            int e = e0 + q * 2;
            float a0 = (f[j * 8 + q * 2 + 0] - mean) * rstd * g[e + 0] + b[e + 0];
            float a1 = (f[j * 8 + q * 2 + 1] - mean) * rstd * g[e + 1] + b[e + 1];
            wh[q] = __floats2half2_rn(a0, a1);
        }
        orow[lane + j * 32] = w;
    }
}

// ---------------- fp16 GEMM: C[M,N] = A[M,512] * Bt[N,512]^T, mma.sync m16n8k16 ----------------
// Tile 128x256x32, 4-stage cp.async pipeline.
#define BM 128
#define BN 256
#define BK 32
#define LDAH 40                      // halves per A row (pad 32->40)
#define LDBH 40
#define A_ST_H (BM*LDAH)             // 5120 halves
#define B_ST_H (BN*LDBH)             // 10240 halves
#define STAGE_H (A_ST_H + B_ST_H)    // 15360 halves = 30720 B
#define NSTG 4
#define GEMM_SMEM (NSTG*STAGE_H*2)   // 122880 bytes

__global__ void __launch_bounds__(256, 1) gemm_fp16(
    const __half* __restrict__ A, const __half* __restrict__ Bt,
    const float* __restrict__ bias, __half* __restrict__ C,
    int Mrows, int Ncols, int dlog2, long long dstride)
{
    extern __shared__ __half smh[];
    const int tid  = threadIdx.x;
    const int warp = tid >> 5, lane = tid & 31;
    const int g = lane >> 2, t = lane & 3;
    const int wm0 = (warp >> 2) * 64;   // 2 warps along M
    const int wn0 = (warp & 3) * 64;    // 4 warps along N
    const int m0 = blockIdx.y * BM;
    const int n0 = blockIdx.x * BN;
    const int dir = n0 >> dlog2;
    const int ncb = n0 & ((1 << dlog2) - 1);
    const __half* Bbase = Bt + (size_t)dir * dstride + (size_t)ncb * EE;

    // fill coords: row = tid>>2 (+64 per pass), 16B chunk col = (tid&3)*8 halves
    const int frow = tid >> 2;
    const int fcol = (tid & 3) * 8;

    float acc[4][8][4];
#pragma unroll
    for (int i = 0; i < 4; i++)
#pragma unroll
        for (int j = 0; j < 8; j++)
#pragma unroll
            for (int k = 0; k < 4; k++) acc[i][j][k] = 0.f;

    auto fill = [&](int kt, int s) {
        __half* Ast = smh + s * STAGE_H;
        __half* Bst = Ast + A_ST_H;
        const int k0 = kt * BK + fcol;
#pragma unroll
        for (int i = 0; i < 2; i++) {
            int r = frow + i * 64;
            int m = m0 + r;
            bool ok = (m < Mrows);
            cp16(su32(Ast + r * LDAH + fcol),
                 A + (size_t)(ok ? m : 0) * EE + k0, ok ? 16 : 0);
        }
#pragma unroll
        for (int i = 0; i < 4; i++) {
            int r = frow + i * 64;
            cp16(su32(Bst + r * LDBH + fcol), Bbase + (size_t)r * EE + k0, 16);
        }
    };

    auto compute = [&](int s) {
        const __half* As = smh + s * STAGE_H;
        const __half* Bs = As + A_ST_H;
#pragma unroll
        for (int ks = 0; ks < 2; ks++) {
            const int kk = ks * 16;
            uint32_t af[4][4], bf[8][2];
#pragma unroll
            for (int i = 0; i < 4; i++) {
                int r = wm0 + i * 16 + g;
                af[i][0] = *(const uint32_t*)(As + (r)     * LDAH + kk + 2 * t);
                af[i][1] = *(const uint32_t*)(As + (r + 8) * LDAH + kk + 2 * t);
                af[i][2] = *(const uint32_t*)(As + (r)     * LDAH + kk + 2 * t + 8);
                af[i][3] = *(const uint32_t*)(As + (r + 8) * LDAH + kk + 2 * t + 8);
            }
#pragma unroll
            for (int j = 0; j < 8; j++) {
                int cn = wn0 + j * 8 + g;
                bf[j][0] = *(const uint32_t*)(Bs + cn * LDBH + kk + 2 * t);
                bf[j][1] = *(const uint32_t*)(Bs + cn * LDBH + kk + 2 * t + 8);
            }
#pragma unroll
            for (int i = 0; i < 4; i++)
#pragma unroll
                for (int j = 0; j < 8; j++)
                    mma_f16(acc[i][j], af[i], bf[j]);
        }
    };

    const int NKT = EE / BK;  // 16

    fill(0, 0); asm volatile("cp.async.commit_group;");
    fill(1, 1); asm volatile("cp.async.commit_group;");
    fill(2, 2); asm volatile("cp.async.commit_group;");
    fill(3, 3); asm volatile("cp.async.commit_group;");

    for (int c = 0; c < NKT; c++) {
        asm volatile("cp.async.wait_group 3;");
        __syncthreads();
        compute(c & 3);
        __syncthreads();
        if (c + NSTG < NKT) fill(c + NSTG, c & 3);
        asm volatile("cp.async.commit_group;");
    }

    // epilogue: fp32 acc (+bias) -> fp16 stores
#pragma unroll
    for (int i = 0; i < 4; i++) {
        int r0 = m0 + wm0 + i * 16 + g;
        int r1 = r0 + 8;
#pragma unroll
        for (int j = 0; j < 8; j++) {
            int cc = n0 + wn0 + j * 8 + 2 * t;
            float b0v = 0.f, b1v = 0.f;
            if (bias) { b0v = bias[cc]; b1v = bias[cc + 1]; }
            if (r0 < Mrows)
                *(__half2*)(C + (size_t)r0 * Ncols + cc) =
                    __floats2half2_rn(acc[i][j][0] + b0v, acc[i][j][1] + b1v);
            if (r1 < Mrows)
                *(__half2*)(C + (size_t)r1 * Ncols + cc) =
                    __floats2half2_rn(acc[i][j][2] + b0v, acc[i][j][3] + b1v);
        }
    }
}

// ---------------- SRU elementwise scan (fp16 U in, fp16 X out) ----------------
__global__ void __launch_bounds__(256) sru_scan(
    const __half* __restrict__ U, const float* __restrict__ v,
    const float* __restrict__ bp, __half* __restrict__ X)
{
    int tid = blockIdx.x * blockDim.x + threadIdx.x;
    if (tid >= 2 * BB * DD) return;
    int dir = tid / (BB * DD);
    int rem = tid - dir * (BB * DD);
    int b = rem / DD;
    int dd = rem - b * DD;

    float vf = v[dir * 2 * DD + dd];
    float vr = v[dir * 2 * DD + DD + dd];
    float bf = bp[dir * 2 * DD + dd];
    float br = bp[dir * 2 * DD + DD + dd];

    const size_t colU = (size_t)dir * 1024 + dd;
    const size_t colX = (size_t)dir * DD + dd;

    float c = 0.f;
    for (int s = 0; s < TT; s++) {
        int t = dir ? (TT - 1 - s) : s;
        const __half* up = U + ((size_t)t * BB + b) * 2048 + colU;
        float u0 = __half2float(up[0]);
        float u1 = __half2float(up[256]);
        float u2 = __half2float(up[512]);
        float u3 = __half2float(up[768]);
        float f = 1.f / (1.f + expf(-(u1 + vf * c + bf)));
        c = f * c + (1.f - f) * u0;
        float r = 1.f / (1.f + expf(-(u2 + vr * c + br)));
        X[((size_t)t * BB + b) * EE + colX] = __float2half_rn(r * c + (1.f - r) * u3);
    }
}

// ---------------- head: BN(eval) + relu + W2 (512x4) + log_softmax; one warp per token ----------------
__global__ void __launch_bounds__(256) head_kernel(
    const __half* __restrict__ h,
    const float* __restrict__ bn_g, const float* __restrict__ bn_b,
    const float* __restrict__ bn_mean, const float* __restrict__ bn_var,
    const float* __restrict__ W2, const float* __restrict__ b2,
    float* __restrict__ out, int Mrows)
{
    __shared__ float w2s[EE * 4];
    __shared__ float scs[EE], tbs[EE];
    __shared__ float b2s[4];
    int tid = threadIdx.x;
    for (int i = tid; i < EE * 4; i += 256) w2s[i] = W2[i];
    for (int i = tid; i < EE; i += 256) {
        float s = bn_g[i] * rsqrtf(bn_var[i] + 1e-5f);
        scs[i] = s;
        tbs[i] = bn_b[i] - bn_mean[i] * s;
    }
    if (tid < 4) b2s[tid] = b2[tid];
    __syncthreads();

    int warp = (blockIdx.x * blockDim.x + tid) >> 5;
    int lane = tid & 31;
    if (warp >= Mrows) return;

    const uint4* hr = (const uint4*)(h + (size_t)warp * EE);  // 8 halves per uint4
    float a0 = 0.f, a1 = 0.f, a2 = 0.f, a3 = 0.f;
#pragma unroll
    for (int j = 0; j < 2; j++) {
        uint4 hv = hr[lane + j * 32];
        const __half2* h2 = (const __half2*)&hv;
        int e0 = (lane + j * 32) * 8;
#pragma unroll
        for (int q = 0; q < 4; q++) {
            float2 p = __half22float2(h2[q]);
            int e = e0 + q * 2;
            float v0 = fmaxf(p.x * scs[e]     + tbs[e],     0.f);
            float v1 = fmaxf(p.y * scs[e + 1] + tbs[e + 1], 0.f);
            a0 += v0 * w2s[e * 4 + 0] + v1 * w2s[(e + 1) * 4 + 0];
            a1 += v0 * w2s[e * 4 + 1] + v1 * w2s[(e + 1) * 4 + 1];
            a2 += v0 * w2s[e * 4 + 2] + v1 * w2s[(e + 1) * 4 + 2];
            a3 += v0 * w2s[e * 4 + 3] + v1 * w2s[(e + 1) * 4 + 3];
        }
    }
#pragma unroll
    for (int o = 16; o > 0; o >>= 1) {
        a0 += __shfl_xor_sync(0xffffffffu, a0, o);
        a1 += __shfl_xor_sync(0xffffffffu, a1, o);
        a2 += __shfl_xor_sync(0xffffffffu, a2, o);
        a3 += __shfl_xor_sync(0xffffffffu, a3, o);
    }
    if (lane == 0) {
        float l0 = a0 + b2s[0], l1 = a1 + b2s[1], l2 = a2 + b2s[2], l3 = a3 + b2s[3];
        float m = fmaxf(fmaxf(l0, l1), fmaxf(l2, l3));
        float se = expf(l0 - m) + expf(l1 - m) + expf(l2 - m) + expf(l3 - m);
        float lse = m + logf(se);
        float4 o = make_float4(l0 - lse, l1 - lse, l2 - lse, l3 - lse);
        ((float4*)out)[warp] = o;
    }
}

// ---------------- launch ----------------
extern "C" void kernel_launch(void* const* d_in, const int* in_sizes, int n_in,
                              void* d_out, int out_size)
{
    const float* sentence = (const float*)d_in[0];
    const float* sru_W    = (const float*)d_in[1];
    const float* sru_v    = (const float*)d_in[2];
    const float* sru_b    = (const float*)d_in[3];
    const float* ln_g     = (const float*)d_in[4];
    const float* ln_b     = (const float*)d_in[5];
    const float* W1       = (const float*)d_in[6];
    const float* b1       = (const float*)d_in[7];
    const float* bn_g     = (const float*)d_in[8];
    const float* bn_b     = (const float*)d_in[9];
    const float* bn_mean  = (const float*)d_in[10];
    const float* bn_var   = (const float*)d_in[11];
    const float* W2       = (const float*)d_in[12];
    const float* b2       = (const float*)d_in[13];
    float* out = (float*)d_out;

    __half *xl, *U, *x, *Wr, *W1r;
    cudaGetSymbolAddress((void**)&xl,  g_xl);
    cudaGetSymbolAddress((void**)&U,   g_U);
    cudaGetSymbolAddress((void**)&x,   g_x);
    cudaGetSymbolAddress((void**)&Wr,  g_Wr);
    cudaGetSymbolAddress((void**)&W1r, g_W1r);

    cudaFuncSetAttribute(gemm_fp16, cudaFuncAttributeMaxDynamicSharedMemorySize, GEMM_SMEM);

    const int M = MROWS;
    const int mtiles = (M + BM - 1) / BM;        // 782
    dim3 gemm_grid_layer(2048 / BN, mtiles);     // (8, 782)
    dim3 gemm_grid_head(EE / BN, mtiles);        // (2, 782)
    int ln_blocks = (M * 32 + 255) / 256;        // 12500
    int scan_blocks = (2 * BB * DD + 255) / 256; // 2000

    // transpose + fp16-round weights
    transpose_half<<<dim3(1024 / 32, EE / 32, LL * 2), 256>>>(sru_W, Wr, EE, 1024);
    transpose_half<<<dim3(EE / 32, EE / 32, 1), 256>>>(W1, W1r, EE, EE);

    for (int l = 0; l < LL; l++) {
        if (l == 0)
            ln_f32<<<ln_blocks, 256>>>(sentence, ln_g, ln_b, xl, M);
        else
            ln_f16<<<ln_blocks, 256>>>(x, ln_g + l * EE, ln_b + l * EE, xl, M);
        gemm_fp16<<<gemm_grid_layer, 256, GEMM_SMEM>>>(
            xl, Wr + (size_t)l * 2 * 1024 * EE, nullptr, U,
            M, 2048, 10, (long long)1024 * EE);
        sru_scan<<<scan_blocks, 256>>>(U, sru_v + l * 4 * DD, sru_b + l * 4 * DD, x);
    }
    // head GEMM: h = x @ W1 + b1 -> xl
    gemm_fp16<<<gemm_grid_head, 256, GEMM_SMEM>>>(
        x, W1r, b1, xl, M, EE, 30, 0LL);
    head_kernel<<<ln_blocks, 256>>>(xl, bn_g, bn_b, bn_mean, bn_var, W2, b2, out, M);
}

// round 8
// speedup vs baseline: 1.9764x; 1.0404x over previous
#include <cuda_runtime.h>
#include <cuda_fp16.h>
#include <cstdint>
#include <cmath>

// Problem constants
#define TT 100
#define BB 1000
#define EE 512
#define DD 256
#define LL 4
#define MROWS (TT*BB)          // 100000

// ---------------- scratch (static device memory; no allocations) ----------------
__device__ __half g_xl[(size_t)MROWS * EE];    // LN output / head hidden (fp16)
__device__ __half g_U [(size_t)MROWS * 2048];  // projected gates (fp16)
__device__ __half g_x [(size_t)MROWS * EE];    // layer activations (fp16)
__device__ __half g_Wr [(size_t)LL * 2 * 1024 * EE]; // transposed+rounded sru_W: [l,d][n,k]
__device__ __half g_W1r[(size_t)EE * EE];            // transposed+rounded W1: [n,k]

// ---------------- helpers ----------------
__device__ __forceinline__ uint32_t su32(const void* p) {
    return (uint32_t)__cvta_generic_to_shared(p);
}

__device__ __forceinline__ void cp16(uint32_t dst, const void* src, int sz) {
    asm volatile("cp.async.ca.shared.global [%0], [%1], 16, %2;" :: "r"(dst), "l"(src), "r"(sz));
}

__device__ __forceinline__ void mma_f16(float c[4], const uint32_t a[4], const uint32_t b[2]) {
    asm volatile(
        "mma.sync.aligned.m16n8k16.row.col.f32.f16.f16.f32 "
        "{%0,%1,%2,%3}, {%4,%5,%6,%7}, {%8,%9}, {%0,%1,%2,%3};\n"
        : "+f"(c[0]), "+f"(c[1]), "+f"(c[2]), "+f"(c[3])
        : "r"(a[0]), "r"(a[1]), "r"(a[2]), "r"(a[3]), "r"(b[0]), "r"(b[1]));
}

__device__ __forceinline__ void ldsm4(uint32_t& r0, uint32_t& r1, uint32_t& r2, uint32_t& r3,
                                      uint32_t addr) {
    asm volatile("ldmatrix.sync.aligned.m8n8.x4.shared.b16 {%0,%1,%2,%3}, [%4];"
                 : "=r"(r0), "=r"(r1), "=r"(r2), "=r"(r3) : "r"(addr));
}

// ---------------- transpose + fp16 round: [K,N] -> [N,K] per batch ----------------
__global__ void __launch_bounds__(256) transpose_half(
    const float* __restrict__ in, __half* __restrict__ out, int K, int N)
{
    __shared__ float tile[32][33];
    int b = blockIdx.z;
    const float* ip = in + (size_t)b * K * N;
    __half* op = out + (size_t)b * K * N;
    int k0 = blockIdx.y * 32, n0 = blockIdx.x * 32;
    int tx = threadIdx.x & 31, ty = threadIdx.x >> 5;  // 32x8
#pragma unroll
    for (int i = 0; i < 32; i += 8)
        tile[ty + i][tx] = ip[(size_t)(k0 + ty + i) * N + n0 + tx];
    __syncthreads();
#pragma unroll
    for (int i = 0; i < 32; i += 8)
        op[(size_t)(n0 + ty + i) * K + k0 + tx] = __float2half_rn(tile[tx][ty + i]);
}

// ---------------- LayerNorm (fp32 input, fp16 output): one warp per token ----------------
__global__ void __launch_bounds__(256) ln_f32(
    const float* __restrict__ x, const float* __restrict__ g,
    const float* __restrict__ b, __half* __restrict__ out, int Mrows)
{
    int warp = (blockIdx.x * blockDim.x + threadIdx.x) >> 5;
    int lane = threadIdx.x & 31;
    if (warp >= Mrows) return;

    const float4* xr = (const float4*)(x + (size_t)warp * EE);
    float4 v[4];
    float s = 0.f, sq = 0.f;
#pragma unroll
    for (int j = 0; j < 4; j++) {
        v[j] = xr[lane + j * 32];
        s  += v[j].x + v[j].y + v[j].z + v[j].w;
        sq += v[j].x*v[j].x + v[j].y*v[j].y + v[j].z*v[j].z + v[j].w*v[j].w;
    }
#pragma unroll
    for (int o = 16; o > 0; o >>= 1) {
        s  += __shfl_xor_sync(0xffffffffu, s, o);
        sq += __shfl_xor_sync(0xffffffffu, sq, o);
    }
    float mean = s * (1.f / EE);
    float var  = sq * (1.f / EE) - mean * mean;
    float rstd = rsqrtf(var + 1e-5f);

    __half2* orow = (__half2*)(out + (size_t)warp * EE);
    const float4* gg4 = (const float4*)g;
    const float4* bb4 = (const float4*)b;
#pragma unroll
    for (int j = 0; j < 4; j++) {
        int e4 = lane + j * 32;
        float4 gg = gg4[e4], bb = bb4[e4];
        float w0 = (v[j].x - mean) * rstd * gg.x + bb.x;
        float w1 = (v[j].y - mean) * rstd * gg.y + bb.y;
        float w2 = (v[j].z - mean) * rstd * gg.z + bb.z;
        float w3 = (v[j].w - mean) * rstd * gg.w + bb.w;
        orow[e4 * 2 + 0] = __floats2half2_rn(w0, w1);
        orow[e4 * 2 + 1] = __floats2half2_rn(w2, w3);
    }
}

// ---------------- LayerNorm (fp16 input, fp16 output) ----------------
__global__ void __launch_bounds__(256) ln_f16(
    const __half* __restrict__ x, const float* __restrict__ g,
    const float* __restrict__ b, __half* __restrict__ out, int Mrows)
{
    int warp = (blockIdx.x * blockDim.x + threadIdx.x) >> 5;
    int lane = threadIdx.x & 31;
    if (warp >= Mrows) return;

    const uint4* xr = (const uint4*)(x + (size_t)warp * EE);  // 8 halves per uint4
    uint4 v[2];
    float f[16];
    float s = 0.f, sq = 0.f;
#pragma unroll
    for (int j = 0; j < 2; j++) {
        v[j] = xr[lane + j * 32];
        const __half2* h2 = (const __half2*)&v[j];
#pragma unroll
        for (int q = 0; q < 4; q++) {
            float2 p = __half22float2(h2[q]);
            f[j * 8 + q * 2 + 0] = p.x;
            f[j * 8 + q * 2 + 1] = p.y;
            s += p.x + p.y;
            sq += p.x * p.x + p.y * p.y;
        }
    }
#pragma unroll
    for (int o = 16; o > 0; o >>= 1) {
        s  += __shfl_xor_sync(0xffffffffu, s, o);
        sq += __shfl_xor_sync(0xffffffffu, sq, o);
    }
    float mean = s * (1.f / EE);
    float var  = sq * (1.f / EE) - mean * mean;
    float rstd = rsqrtf(var + 1e-5f);

    uint4* orow = (uint4*)(out + (size_t)warp * EE);
#pragma unroll
    for (int j = 0; j < 2; j++) {
        int e0 = (lane + j * 32) * 8;
        uint4 w;
        __half2* wh = (__half2*)&w;
#pragma unroll
        for (int q = 0; q < 4; q++) {
            int e = e0 + q * 2;
            float a0 = (f[j * 8 + q * 2 + 0] - mean) * rstd * g[e + 0] + b[e + 0];
            float a1 = (f[j * 8 + q * 2 + 1] - mean) * rstd * g[e + 1] + b[e + 1];
            wh[q] = __floats2half2_rn(a0, a1);
        }
        orow[lane + j * 32] = w;
    }
}

// ---------------- fp16 GEMM: C[M,N] = A[M,512] * Bt[N,512]^T, mma.sync m16n8k16 ----------------
// Tile 128x256x32, 4-stage cp.async pipeline, single barrier per chunk, ldmatrix frags.
#define BM 128
#define BN 256
#define BK 32
#define LDAH 40                      // halves per A row (pad 32->40)
#define LDBH 40
#define A_ST_H (BM*LDAH)             // 5120 halves
#define B_ST_H (BN*LDBH)             // 10240 halves
#define STAGE_H (A_ST_H + B_ST_H)    // 15360 halves = 30720 B
#define NSTG 4
#define GEMM_SMEM (NSTG*STAGE_H*2)   // 122880 bytes

__global__ void __launch_bounds__(256, 1) gemm_fp16(
    const __half* __restrict__ A, const __half* __restrict__ Bt,
    const float* __restrict__ bias, __half* __restrict__ C,
    int Mrows, int Ncols, int dlog2, long long dstride)
{
    extern __shared__ __half smh[];
    const int tid  = threadIdx.x;
    const int warp = tid >> 5, lane = tid & 31;
    const int g = lane >> 2, t = lane & 3;
    const int wm0 = (warp >> 2) * 64;   // 2 warps along M
    const int wn0 = (warp & 3) * 64;    // 4 warps along N
    const int m0 = blockIdx.y * BM;
    const int n0 = blockIdx.x * BN;
    const int dir = n0 >> dlog2;
    const int ncb = n0 & ((1 << dlog2) - 1);
    const __half* Bbase = Bt + (size_t)dir * dstride + (size_t)ncb * EE;

    // fill coords: row = tid>>2 (+64 per pass), 16B chunk col = (tid&3)*8 halves
    const int frow = tid >> 2;
    const int fcol = (tid & 3) * 8;

    // ldmatrix lane offsets (bytes)
    const uint32_t a_lane = ((lane & 15) * LDAH + (lane >> 4) * 8) * 2;
    const uint32_t b_lane = (((lane & 7) + (lane >> 4) * 8) * LDBH + ((lane >> 3) & 1) * 8) * 2;

    float acc[4][8][4];
#pragma unroll
    for (int i = 0; i < 4; i++)
#pragma unroll
        for (int j = 0; j < 8; j++)
#pragma unroll
            for (int k = 0; k < 4; k++) acc[i][j][k] = 0.f;

    auto fill = [&](int kt, int s) {
        __half* Ast = smh + s * STAGE_H;
        __half* Bst = Ast + A_ST_H;
        const int k0 = kt * BK + fcol;
#pragma unroll
        for (int i = 0; i < 2; i++) {
            int r = frow + i * 64;
            int m = m0 + r;
            bool ok = (m < Mrows);
            cp16(su32(Ast + r * LDAH + fcol),
                 A + (size_t)(ok ? m : 0) * EE + k0, ok ? 16 : 0);
        }
#pragma unroll
        for (int i = 0; i < 4; i++) {
            int r = frow + i * 64;
            cp16(su32(Bst + r * LDBH + fcol), Bbase + (size_t)r * EE + k0, 16);
        }
    };

    auto compute = [&](int s) {
        const uint32_t a_base = su32(smh + s * STAGE_H) + a_lane;
        const uint32_t b_base = su32(smh + s * STAGE_H + A_ST_H) + b_lane;
#pragma unroll
        for (int ks = 0; ks < 2; ks++) {
            const int kk = ks * 16;
            uint32_t af[4][4], bf[8][2];
#pragma unroll
            for (int i = 0; i < 4; i++)
                ldsm4(af[i][0], af[i][1], af[i][2], af[i][3],
                      a_base + ((wm0 + i * 16) * LDAH + kk) * 2);
#pragma unroll
            for (int jp = 0; jp < 4; jp++) {
                int j = jp * 2;
                ldsm4(bf[j][0], bf[j][1], bf[j + 1][0], bf[j + 1][1],
                      b_base + ((wn0 + j * 8) * LDBH + kk) * 2);
            }
#pragma unroll
            for (int i = 0; i < 4; i++)
#pragma unroll
                for (int j = 0; j < 8; j++)
                    mma_f16(acc[i][j], af[i], bf[j]);
        }
    };

    const int NKT = EE / BK;  // 16

    fill(0, 0); asm volatile("cp.async.commit_group;");
    fill(1, 1); asm volatile("cp.async.commit_group;");
    fill(2, 2); asm volatile("cp.async.commit_group;");

    for (int c = 0; c < NKT; c++) {
        asm volatile("cp.async.wait_group 2;");
        __syncthreads();
        if (c + 3 < NKT) fill(c + 3, (c + 3) & 3);
        asm volatile("cp.async.commit_group;");
        compute(c & 3);
    }

    // epilogue: fp32 acc (+bias) -> fp16 stores
#pragma unroll
    for (int i = 0; i < 4; i++) {
        int r0 = m0 + wm0 + i * 16 + g;
        int r1 = r0 + 8;
#pragma unroll
        for (int j = 0; j < 8; j++) {
            int cc = n0 + wn0 + j * 8 + 2 * t;
            float b0v = 0.f, b1v = 0.f;
            if (bias) { b0v = bias[cc]; b1v = bias[cc + 1]; }
            if (r0 < Mrows)
                *(__half2*)(C + (size_t)r0 * Ncols + cc) =
                    __floats2half2_rn(acc[i][j][0] + b0v, acc[i][j][1] + b1v);
            if (r1 < Mrows)
                *(__half2*)(C + (size_t)r1 * Ncols + cc) =
                    __floats2half2_rn(acc[i][j][2] + b0v, acc[i][j][3] + b1v);
        }
    }
}

// ---------------- SRU elementwise scan (fp16 U in, fp16 X out) ----------------
__global__ void __launch_bounds__(256) sru_scan(
    const __half* __restrict__ U, const float* __restrict__ v,
    const float* __restrict__ bp, __half* __restrict__ X)
{
    int tid = blockIdx.x * blockDim.x + threadIdx.x;
    if (tid >= 2 * BB * DD) return;
    int dir = tid / (BB * DD);
    int rem = tid - dir * (BB * DD);
    int b = rem / DD;
    int dd = rem - b * DD;

    float vf = v[dir * 2 * DD + dd];
    float vr = v[dir * 2 * DD + DD + dd];
    float bf = bp[dir * 2 * DD + dd];
    float br = bp[dir * 2 * DD + DD + dd];

    const size_t colU = (size_t)dir * 1024 + dd;
    const size_t colX = (size_t)dir * DD + dd;

    float c = 0.f;
    for (int s = 0; s < TT; s++) {
        int t = dir ? (TT - 1 - s) : s;
        const __half* up = U + ((size_t)t * BB + b) * 2048 + colU;
        float u0 = __half2float(up[0]);
        float u1 = __half2float(up[256]);
        float u2 = __half2float(up[512]);
        float u3 = __half2float(up[768]);
        float f = 1.f / (1.f + expf(-(u1 + vf * c + bf)));
        c = f * c + (1.f - f) * u0;
        float r = 1.f / (1.f + expf(-(u2 + vr * c + br)));
        X[((size_t)t * BB + b) * EE + colX] = __float2half_rn(r * c + (1.f - r) * u3);
    }
}

// ---------------- head: BN(eval) + relu + W2 (512x4) + log_softmax; one warp per token ----------------
__global__ void __launch_bounds__(256) head_kernel(
    const __half* __restrict__ h,
    const float* __restrict__ bn_g, const float* __restrict__ bn_b,
    const float* __restrict__ bn_mean, const float* __restrict__ bn_var,
    const float* __restrict__ W2, const float* __restrict__ b2,
    float* __restrict__ out, int Mrows)
{
    __shared__ float w2s[EE * 4];
    __shared__ float scs[EE], tbs[EE];
    __shared__ float b2s[4];
    int tid = threadIdx.x;
    for (int i = tid; i < EE * 4; i += 256) w2s[i] = W2[i];
    for (int i = tid; i < EE; i += 256) {
        float s = bn_g[i] * rsqrtf(bn_var[i] + 1e-5f);
        scs[i] = s;
        tbs[i] = bn_b[i] - bn_mean[i] * s;
    }
    if (tid < 4) b2s[tid] = b2[tid];
    __syncthreads();

    int warp = (blockIdx.x * blockDim.x + tid) >> 5;
    int lane = tid & 31;
    if (warp >= Mrows) return;

    const uint4* hr = (const uint4*)(h + (size_t)warp * EE);  // 8 halves per uint4
    float a0 = 0.f, a1 = 0.f, a2 = 0.f, a3 = 0.f;
#pragma unroll
    for (int j = 0; j < 2; j++) {
        uint4 hv = hr[lane + j * 32];
        const __half2* h2 = (const __half2*)&hv;
        int e0 = (lane + j * 32) * 8;
#pragma unroll
        for (int q = 0; q < 4; q++) {
            float2 p = __half22float2(h2[q]);
            int e = e0 + q * 2;
            float v0 = fmaxf(p.x * scs[e]     + tbs[e],     0.f);
            float v1 = fmaxf(p.y * scs[e + 1] + tbs[e + 1], 0.f);
            a0 += v0 * w2s[e * 4 + 0] + v1 * w2s[(e + 1) * 4 + 0];
            a1 += v0 * w2s[e * 4 + 1] + v1 * w2s[(e + 1) * 4 + 1];
            a2 += v0 * w2s[e * 4 + 2] + v1 * w2s[(e + 1) * 4 + 2];
            a3 += v0 * w2s[e * 4 + 3] + v1 * w2s[(e + 1) * 4 + 3];
        }
    }
#pragma unroll
    for (int o = 16; o > 0; o >>= 1) {
        a0 += __shfl_xor_sync(0xffffffffu, a0, o);
        a1 += __shfl_xor_sync(0xffffffffu, a1, o);
        a2 += __shfl_xor_sync(0xffffffffu, a2, o);
        a3 += __shfl_xor_sync(0xffffffffu, a3, o);
    }
    if (lane == 0) {
        float l0 = a0 + b2s[0], l1 = a1 + b2s[1], l2 = a2 + b2s[2], l3 = a3 + b2s[3];
        float m = fmaxf(fmaxf(l0, l1), fmaxf(l2, l3));
        float se = expf(l0 - m) + expf(l1 - m) + expf(l2 - m) + expf(l3 - m);
        float lse = m + logf(se);
        float4 o = make_float4(l0 - lse, l1 - lse, l2 - lse, l3 - lse);
        ((float4*)out)[warp] = o;
    }
}

// ---------------- launch ----------------
extern "C" void kernel_launch(void* const* d_in, const int* in_sizes, int n_in,
                              void* d_out, int out_size)
{
    const float* sentence = (const float*)d_in[0];
    const float* sru_W    = (const float*)d_in[1];
    const float* sru_v    = (const float*)d_in[2];
    const float* sru_b    = (const float*)d_in[3];
    const float* ln_g     = (const float*)d_in[4];
    const float* ln_b     = (const float*)d_in[5];
    const float* W1       = (const float*)d_in[6];
    const float* b1       = (const float*)d_in[7];
    const float* bn_g     = (const float*)d_in[8];
    const float* bn_b     = (const float*)d_in[9];
    const float* bn_mean  = (const float*)d_in[10];
    const float* bn_var   = (const float*)d_in[11];
    const float* W2       = (const float*)d_in[12];
    const float* b2       = (const float*)d_in[13];
    float* out = (float*)d_out;

    __half *xl, *U, *x, *Wr, *W1r;
    cudaGetSymbolAddress((void**)&xl,  g_xl);
    cudaGetSymbolAddress((void**)&U,   g_U);
    cudaGetSymbolAddress((void**)&x,   g_x);
    cudaGetSymbolAddress((void**)&Wr,  g_Wr);
    cudaGetSymbolAddress((void**)&W1r, g_W1r);

    cudaFuncSetAttribute(gemm_fp16, cudaFuncAttributeMaxDynamicSharedMemorySize, GEMM_SMEM);

    const int M = MROWS;
    const int mtiles = (M + BM - 1) / BM;        // 782
    dim3 gemm_grid_layer(2048 / BN, mtiles);     // (8, 782)
    dim3 gemm_grid_head(EE / BN, mtiles);        // (2, 782)
    int ln_blocks = (M * 32 + 255) / 256;        // 12500
    int scan_blocks = (2 * BB * DD + 255) / 256; // 2000

    // transpose + fp16-round weights
    transpose_half<<<dim3(1024 / 32, EE / 32, LL * 2), 256>>>(sru_W, Wr, EE, 1024);
    transpose_half<<<dim3(EE / 32, EE / 32, 1), 256>>>(W1, W1r, EE, EE);

    for (int l = 0; l < LL; l++) {
        if (l == 0)
            ln_f32<<<ln_blocks, 256>>>(sentence, ln_g, ln_b, xl, M);
        else
            ln_f16<<<ln_blocks, 256>>>(x, ln_g + l * EE, ln_b + l * EE, xl, M);
        gemm_fp16<<<gemm_grid_layer, 256, GEMM_SMEM>>>(
            xl, Wr + (size_t)l * 2 * 1024 * EE, nullptr, U,
            M, 2048, 10, (long long)1024 * EE);
        sru_scan<<<scan_blocks, 256>>>(U, sru_v + l * 4 * DD, sru_b + l * 4 * DD, x);
    }
    // head GEMM: h = x @ W1 + b1 -> xl
    gemm_fp16<<<gemm_grid_head, 256, GEMM_SMEM>>>(
        x, W1r, b1, xl, M, EE, 30, 0LL);
    head_kernel<<<ln_blocks, 256>>>(xl, bn_g, bn_b, bn_mean, bn_var, W2, b2, out, M);
}

// round 9
// speedup vs baseline: 2.0036x; 1.0137x over previous
#include <cuda_runtime.h>
#include <cuda_fp16.h>
#include <cstdint>
#include <cmath>

// Problem constants
#define TT 100
#define BB 1000
#define EE 512
#define DD 256
#define LL 4
#define MROWS (TT*BB)          // 100000

// ---------------- scratch (static device memory; no allocations) ----------------
__device__ __half g_xl[(size_t)MROWS * EE];    // LN output / head hidden (fp16)
__device__ __half g_U [(size_t)MROWS * 2048];  // projected gates (fp16)
__device__ __half g_x [(size_t)MROWS * EE];    // layer activations (fp16)
__device__ __half g_Wr [(size_t)LL * 2 * 1024 * EE]; // transposed+rounded sru_W: [l,d][n,k]
__device__ __half g_W1r[(size_t)EE * EE];            // transposed+rounded W1: [n,k]

// ---------------- helpers ----------------
__device__ __forceinline__ uint32_t su32(const void* p) {
    return (uint32_t)__cvta_generic_to_shared(p);
}

__device__ __forceinline__ void cp16(uint32_t dst, const void* src, int sz) {
    asm volatile("cp.async.ca.shared.global [%0], [%1], 16, %2;" :: "r"(dst), "l"(src), "r"(sz));
}

__device__ __forceinline__ void mma_f16(float c[4], const uint32_t a[4], const uint32_t b[2]) {
    asm volatile(
        "mma.sync.aligned.m16n8k16.row.col.f32.f16.f16.f32 "
        "{%0,%1,%2,%3}, {%4,%5,%6,%7}, {%8,%9}, {%0,%1,%2,%3};\n"
        : "+f"(c[0]), "+f"(c[1]), "+f"(c[2]), "+f"(c[3])
        : "r"(a[0]), "r"(a[1]), "r"(a[2]), "r"(a[3]), "r"(b[0]), "r"(b[1]));
}

__device__ __forceinline__ void ldsm4(uint32_t& r0, uint32_t& r1, uint32_t& r2, uint32_t& r3,
                                      uint32_t addr) {
    asm volatile("ldmatrix.sync.aligned.m8n8.x4.shared.b16 {%0,%1,%2,%3}, [%4];"
                 : "=r"(r0), "=r"(r1), "=r"(r2), "=r"(r3) : "r"(addr));
}

// ---------------- transpose + fp16 round: [K,N] -> [N,K] per batch ----------------
__global__ void __launch_bounds__(256) transpose_half(
    const float* __restrict__ in, __half* __restrict__ out, int K, int N)
{
    __shared__ float tile[32][33];
    int b = blockIdx.z;
    const float* ip = in + (size_t)b * K * N;
    __half* op = out + (size_t)b * K * N;
    int k0 = blockIdx.y * 32, n0 = blockIdx.x * 32;
    int tx = threadIdx.x & 31, ty = threadIdx.x >> 5;  // 32x8
#pragma unroll
    for (int i = 0; i < 32; i += 8)
        tile[ty + i][tx] = ip[(size_t)(k0 + ty + i) * N + n0 + tx];
    __syncthreads();
#pragma unroll
    for (int i = 0; i < 32; i += 8)
        op[(size_t)(n0 + ty + i) * K + k0 + tx] = __float2half_rn(tile[tx][ty + i]);
}

// ---------------- LayerNorm (fp32 input, fp16 output): one warp per token ----------------
__global__ void __launch_bounds__(256) ln_f32(
    const float* __restrict__ x, const float* __restrict__ g,
    const float* __restrict__ b, __half* __restrict__ out, int Mrows)
{
    int warp = (blockIdx.x * blockDim.x + threadIdx.x) >> 5;
    int lane = threadIdx.x & 31;
    if (warp >= Mrows) return;

    const float4* xr = (const float4*)(x + (size_t)warp * EE);
    float4 v[4];
    float s = 0.f, sq = 0.f;
#pragma unroll
    for (int j = 0; j < 4; j++) {
        v[j] = xr[lane + j * 32];
        s  += v[j].x + v[j].y + v[j].z + v[j].w;
        sq += v[j].x*v[j].x + v[j].y*v[j].y + v[j].z*v[j].z + v[j].w*v[j].w;
    }
#pragma unroll
    for (int o = 16; o > 0; o >>= 1) {
        s  += __shfl_xor_sync(0xffffffffu, s, o);
        sq += __shfl_xor_sync(0xffffffffu, sq, o);
    }
    float mean = s * (1.f / EE);
    float var  = sq * (1.f / EE) - mean * mean;
    float rstd = rsqrtf(var + 1e-5f);

    __half2* orow = (__half2*)(out + (size_t)warp * EE);
    const float4* gg4 = (const float4*)g;
    const float4* bb4 = (const float4*)b;
#pragma unroll
    for (int j = 0; j < 4; j++) {
        int e4 = lane + j * 32;
        float4 gg = gg4[e4], bb = bb4[e4];
        float w0 = (v[j].x - mean) * rstd * gg.x + bb.x;
        float w1 = (v[j].y - mean) * rstd * gg.y + bb.y;
        float w2 = (v[j].z - mean) * rstd * gg.z + bb.z;
        float w3 = (v[j].w - mean) * rstd * gg.w + bb.w;
        orow[e4 * 2 + 0] = __floats2half2_rn(w0, w1);
        orow[e4 * 2 + 1] = __floats2half2_rn(w2, w3);
    }
}

// ---------------- LayerNorm (fp16 input, fp16 output) ----------------
__global__ void __launch_bounds__(256) ln_f16(
    const __half* __restrict__ x, const float* __restrict__ g,
    const float* __restrict__ b, __half* __restrict__ out, int Mrows)
{
    int warp = (blockIdx.x * blockDim.x + threadIdx.x) >> 5;
    int lane = threadIdx.x & 31;
    if (warp >= Mrows) return;

    const uint4* xr = (const uint4*)(x + (size_t)warp * EE);  // 8 halves per uint4
    uint4 v[2];
    float f[16];
    float s = 0.f, sq = 0.f;
#pragma unroll
    for (int j = 0; j < 2; j++) {
        v[j] = xr[lane + j * 32];
        const __half2* h2 = (const __half2*)&v[j];
#pragma unroll
        for (int q = 0; q < 4; q++) {
            float2 p = __half22float2(h2[q]);
            f[j * 8 + q * 2 + 0] = p.x;
            f[j * 8 + q * 2 + 1] = p.y;
            s += p.x + p.y;
            sq += p.x * p.x + p.y * p.y;
        }
    }
#pragma unroll
    for (int o = 16; o > 0; o >>= 1) {
        s  += __shfl_xor_sync(0xffffffffu, s, o);
        sq += __shfl_xor_sync(0xffffffffu, sq, o);
    }
    float mean = s * (1.f / EE);
    float var  = sq * (1.f / EE) - mean * mean;
    float rstd = rsqrtf(var + 1e-5f);

    uint4* orow = (uint4*)(out + (size_t)warp * EE);
#pragma unroll
    for (int j = 0; j < 2; j++) {
        int e0 = (lane + j * 32) * 8;
        uint4 w;
        __half2* wh = (__half2*)&w;
#pragma unroll
        for (int q = 0; q < 4; q++) {
            int e = e0 + q * 2;
            float a0 = (f[j * 8 + q * 2 + 0] - mean) * rstd * g[e + 0] + b[e + 0];
            float a1 = (f[j * 8 + q * 2 + 1] - mean) * rstd * g[e + 1] + b[e + 1];
            wh[q] = __floats2half2_rn(a0, a1);
        }
        orow[lane + j * 32] = w;
    }
}

// ---------------- fp16 GEMM: C[M,N] = A[M,512] * Bt[N,512]^T, mma.sync m16n8k16 ----------------
// Tile 128x256x32, 4-stage cp.async pipeline, single barrier per chunk.
// SW64-swizzled 64B rows (32 halves): 16B chunk c stored at c ^ ((row>>1)&3).
// Conflict-free for both cp.async stores and ldmatrix x4 reads.
#define BM 128
#define BN 256
#define BK 32
#define A_BYT (BM*64)                // 8192
#define B_BYT (BN*64)                // 16384
#define STG_BYT (A_BYT + B_BYT)      // 24576
#define NSTG 4
#define GEMM_SMEM (NSTG*STG_BYT + 128)

__global__ void __launch_bounds__(256, 1) gemm_fp16(
    const __half* __restrict__ A, const __half* __restrict__ Bt,
    const float* __restrict__ bias, __half* __restrict__ C,
    int Mrows, int Ncols, int dlog2, long long dstride)
{
    extern __shared__ __half smh[];
    const uint32_t ub = (su32(smh) + 127u) & ~127u;   // 128B-aligned smem base

    const int tid  = threadIdx.x;
    const int warp = tid >> 5, lane = tid & 31;
    const int g = lane >> 2, t = lane & 3;
    const int wm0 = (warp >> 2) * 64;   // 2 warps along M
    const int wn0 = (warp & 3) * 64;    // 4 warps along N
    const int m0 = blockIdx.y * BM;
    const int n0 = blockIdx.x * BN;
    const int dir = n0 >> dlog2;
    const int ncb = n0 & ((1 << dlog2) - 1);
    const __half* Bbase = Bt + (size_t)dir * dstride + (size_t)ncb * EE;

    // fill coords: row = tid>>2 (+64 per pass), swizzled 16B chunk
    const int frow = tid >> 2;
    const uint32_t fsw16 = (uint32_t)(((tid & 3) ^ ((frow >> 1) & 3)) * 16);
    const int fcol = (tid & 3) * 8;    // source col in halves

    // ldmatrix per-lane swizzled byte offsets (kk=0); kk=16 -> XOR 32
    const int ar = lane & 15;
    const uint32_t a_lane = (uint32_t)(ar * 64 + (((lane >> 4) ^ ((ar >> 1) & 3)) * 16));
    const int br = (lane & 7) | (((lane >> 4) & 1) << 3);
    const uint32_t b_lane = (uint32_t)(br * 64 + ((((lane >> 3) & 1) ^ ((br >> 1) & 3)) * 16));

    float acc[4][8][4];
#pragma unroll
    for (int i = 0; i < 4; i++)
#pragma unroll
        for (int j = 0; j < 8; j++)
#pragma unroll
            for (int k = 0; k < 4; k++) acc[i][j][k] = 0.f;

    auto fill = [&](int kt, int s) {
        uint32_t Ast = ub + s * STG_BYT;
        uint32_t Bst = Ast + A_BYT;
        const int k0 = kt * BK + fcol;
#pragma unroll
        for (int i = 0; i < 2; i++) {
            int r = frow + i * 64;
            int m = m0 + r;
            bool ok = (m < Mrows);
            cp16(Ast + (uint32_t)(r * 64) + fsw16,
                 A + (size_t)(ok ? m : 0) * EE + k0, ok ? 16 : 0);
        }
#pragma unroll
        for (int i = 0; i < 4; i++) {
            int r = frow + i * 64;
            cp16(Bst + (uint32_t)(r * 64) + fsw16, Bbase + (size_t)r * EE + k0, 16);
        }
    };

    auto compute = [&](int s) {
        const uint32_t a_base = ub + s * STG_BYT + a_lane;
        const uint32_t b_base = ub + s * STG_BYT + A_BYT + b_lane;
#pragma unroll
        for (int ks = 0; ks < 2; ks++) {
            const uint32_t kx = ks ? 32u : 0u;
            uint32_t af[4][4], bf[8][2];
#pragma unroll
            for (int i = 0; i < 4; i++)
                ldsm4(af[i][0], af[i][1], af[i][2], af[i][3],
                      (a_base + (uint32_t)((wm0 + i * 16) * 64)) ^ kx);
#pragma unroll
            for (int jp = 0; jp < 4; jp++) {
                int j = jp * 2;
                ldsm4(bf[j][0], bf[j][1], bf[j + 1][0], bf[j + 1][1],
                      (b_base + (uint32_t)((wn0 + j * 8) * 64)) ^ kx);
            }
#pragma unroll
            for (int i = 0; i < 4; i++)
#pragma unroll
                for (int j = 0; j < 8; j++)
                    mma_f16(acc[i][j], af[i], bf[j]);
        }
    };

    const int NKT = EE / BK;  // 16

    fill(0, 0); asm volatile("cp.async.commit_group;");
    fill(1, 1); asm volatile("cp.async.commit_group;");
    fill(2, 2); asm volatile("cp.async.commit_group;");

    for (int c = 0; c < NKT; c++) {
        asm volatile("cp.async.wait_group 2;");
        __syncthreads();
        if (c + 3 < NKT) fill(c + 3, (c + 3) & 3);
        asm volatile("cp.async.commit_group;");
        compute(c & 3);
    }

    // epilogue: fp32 acc (+bias) -> fp16 stores
#pragma unroll
    for (int i = 0; i < 4; i++) {
        int r0 = m0 + wm0 + i * 16 + g;
        int r1 = r0 + 8;
#pragma unroll
        for (int j = 0; j < 8; j++) {
            int cc = n0 + wn0 + j * 8 + 2 * t;
            float b0v = 0.f, b1v = 0.f;
            if (bias) { b0v = bias[cc]; b1v = bias[cc + 1]; }
            if (r0 < Mrows)
                *(__half2*)(C + (size_t)r0 * Ncols + cc) =
                    __floats2half2_rn(acc[i][j][0] + b0v, acc[i][j][1] + b1v);
            if (r1 < Mrows)
                *(__half2*)(C + (size_t)r1 * Ncols + cc) =
                    __floats2half2_rn(acc[i][j][2] + b0v, acc[i][j][3] + b1v);
        }
    }
}

// ---------------- SRU elementwise scan (fp16 U in, fp16 X out) ----------------
__global__ void __launch_bounds__(256) sru_scan(
    const __half* __restrict__ U, const float* __restrict__ v,
    const float* __restrict__ bp, __half* __restrict__ X)
{
    int tid = blockIdx.x * blockDim.x + threadIdx.x;
    if (tid >= 2 * BB * DD) return;
    int dir = tid / (BB * DD);
    int rem = tid - dir * (BB * DD);
    int b = rem / DD;
    int dd = rem - b * DD;

    float vf = v[dir * 2 * DD + dd];
    float vr = v[dir * 2 * DD + DD + dd];
    float bf = bp[dir * 2 * DD + dd];
    float br = bp[dir * 2 * DD + DD + dd];

    const size_t colU = (size_t)dir * 1024 + dd;
    const size_t colX = (size_t)dir * DD + dd;

    float c = 0.f;
    for (int s = 0; s < TT; s++) {
        int t = dir ? (TT - 1 - s) : s;
        const __half* up = U + ((size_t)t * BB + b) * 2048 + colU;
        float u0 = __half2float(up[0]);
        float u1 = __half2float(up[256]);
        float u2 = __half2float(up[512]);
        float u3 = __half2float(up[768]);
        float f = 1.f / (1.f + expf(-(u1 + vf * c + bf)));
        c = f * c + (1.f - f) * u0;
        float r = 1.f / (1.f + expf(-(u2 + vr * c + br)));
        X[((size_t)t * BB + b) * EE + colX] = __float2half_rn(r * c + (1.f - r) * u3);
    }
}

// ---------------- head: BN(eval) + relu + W2 (512x4) + log_softmax; one warp per token ----------------
__global__ void __launch_bounds__(256) head_kernel(
    const __half* __restrict__ h,
    const float* __restrict__ bn_g, const float* __restrict__ bn_b,
    const float* __restrict__ bn_mean, const float* __restrict__ bn_var,
    const float* __restrict__ W2, const float* __restrict__ b2,
    float* __restrict__ out, int Mrows)
{
    __shared__ float w2s[EE * 4];
    __shared__ float scs[EE], tbs[EE];
    __shared__ float b2s[4];
    int tid = threadIdx.x;
    for (int i = tid; i < EE * 4; i += 256) w2s[i] = W2[i];
    for (int i = tid; i < EE; i += 256) {
        float s = bn_g[i] * rsqrtf(bn_var[i] + 1e-5f);
        scs[i] = s;
        tbs[i] = bn_b[i] - bn_mean[i] * s;
    }
    if (tid < 4) b2s[tid] = b2[tid];
    __syncthreads();

    int warp = (blockIdx.x * blockDim.x + tid) >> 5;
    int lane = tid & 31;
    if (warp >= Mrows) return;

    const uint4* hr = (const uint4*)(h + (size_t)warp * EE);  // 8 halves per uint4
    float a0 = 0.f, a1 = 0.f, a2 = 0.f, a3 = 0.f;
#pragma unroll
    for (int j = 0; j < 2; j++) {
        uint4 hv = hr[lane + j * 32];
        const __half2* h2 = (const __half2*)&hv;
        int e0 = (lane + j * 32) * 8;
#pragma unroll
        for (int q = 0; q < 4; q++) {
            float2 p = __half22float2(h2[q]);
            int e = e0 + q * 2;
            float v0 = fmaxf(p.x * scs[e]     + tbs[e],     0.f);
            float v1 = fmaxf(p.y * scs[e + 1] + tbs[e + 1], 0.f);
            a0 += v0 * w2s[e * 4 + 0] + v1 * w2s[(e + 1) * 4 + 0];
            a1 += v0 * w2s[e * 4 + 1] + v1 * w2s[(e + 1) * 4 + 1];
            a2 += v0 * w2s[e * 4 + 2] + v1 * w2s[(e + 1) * 4 + 2];
            a3 += v0 * w2s[e * 4 + 3] + v1 * w2s[(e + 1) * 4 + 3];
        }
    }
#pragma unroll
    for (int o = 16; o > 0; o >>= 1) {
        a0 += __shfl_xor_sync(0xffffffffu, a0, o);
        a1 += __shfl_xor_sync(0xffffffffu, a1, o);
        a2 += __shfl_xor_sync(0xffffffffu, a2, o);
        a3 += __shfl_xor_sync(0xffffffffu, a3, o);
    }
    if (lane == 0) {
        float l0 = a0 + b2s[0], l1 = a1 + b2s[1], l2 = a2 + b2s[2], l3 = a3 + b2s[3];
        float m = fmaxf(fmaxf(l0, l1), fmaxf(l2, l3));
        float se = expf(l0 - m) + expf(l1 - m) + expf(l2 - m) + expf(l3 - m);
        float lse = m + logf(se);
        float4 o = make_float4(l0 - lse, l1 - lse, l2 - lse, l3 - lse);
        ((float4*)out)[warp] = o;
    }
}

// ---------------- launch ----------------
extern "C" void kernel_launch(void* const* d_in, const int* in_sizes, int n_in,
                              void* d_out, int out_size)
{
    const float* sentence = (const float*)d_in[0];
    const float* sru_W    = (const float*)d_in[1];
    const float* sru_v    = (const float*)d_in[2];
    const float* sru_b    = (const float*)d_in[3];
    const float* ln_g     = (const float*)d_in[4];
    const float* ln_b     = (const float*)d_in[5];
    const float* W1       = (const float*)d_in[6];
    const float* b1       = (const float*)d_in[7];
    const float* bn_g     = (const float*)d_in[8];
    const float* bn_b     = (const float*)d_in[9];
    const float* bn_mean  = (const float*)d_in[10];
    const float* bn_var   = (const float*)d_in[11];
    const float* W2       = (const float*)d_in[12];
    const float* b2       = (const float*)d_in[13];
    float* out = (float*)d_out;

    __half *xl, *U, *x, *Wr, *W1r;
    cudaGetSymbolAddress((void**)&xl,  g_xl);
    cudaGetSymbolAddress((void**)&U,   g_U);
    cudaGetSymbolAddress((void**)&x,   g_x);
    cudaGetSymbolAddress((void**)&Wr,  g_Wr);
    cudaGetSymbolAddress((void**)&W1r, g_W1r);

    cudaFuncSetAttribute(gemm_fp16, cudaFuncAttributeMaxDynamicSharedMemorySize, GEMM_SMEM);

    const int M = MROWS;
    const int mtiles = (M + BM - 1) / BM;        // 782
    dim3 gemm_grid_layer(2048 / BN, mtiles);     // (8, 782)
    dim3 gemm_grid_head(EE / BN, mtiles);        // (2, 782)
    int ln_blocks = (M * 32 + 255) / 256;        // 12500
    int scan_blocks = (2 * BB * DD + 255) / 256; // 2000

    // transpose + fp16-round weights
    transpose_half<<<dim3(1024 / 32, EE / 32, LL * 2), 256>>>(sru_W, Wr, EE, 1024);
    transpose_half<<<dim3(EE / 32, EE / 32, 1), 256>>>(W1, W1r, EE, EE);

    for (int l = 0; l < LL; l++) {
        if (l == 0)
            ln_f32<<<ln_blocks, 256>>>(sentence, ln_g, ln_b, xl, M);
        else
            ln_f16<<<ln_blocks, 256>>>(x, ln_g + l * EE, ln_b + l * EE, xl, M);
        gemm_fp16<<<gemm_grid_layer, 256, GEMM_SMEM>>>(
            xl, Wr + (size_t)l * 2 * 1024 * EE, nullptr, U,
            M, 2048, 10, (long long)1024 * EE);
        sru_scan<<<scan_blocks, 256>>>(U, sru_v + l * 4 * DD, sru_b + l * 4 * DD, x);
    }
    // head GEMM: h = x @ W1 + b1 -> xl
    gemm_fp16<<<gemm_grid_head, 256, GEMM_SMEM>>>(
        x, W1r, b1, xl, M, EE, 30, 0LL);
    head_kernel<<<ln_blocks, 256>>>(xl, bn_g, bn_b, bn_mean, bn_var, W2, b2, out, M);
}

// round 13
// speedup vs baseline: 2.4070x; 1.2013x over previous
#include <cuda_runtime.h>
#include <cuda_fp16.h>
#include <cstdint>
#include <cmath>

// Problem constants
#define TT 100
#define BB 1000
#define EE 512
#define DD 256
#define LL 4
#define MROWS (TT*BB)          // 100000

// ---------------- scratch (static device memory; no allocations) ----------------
__device__ __half g_xl[(size_t)MROWS * EE];    // LN output / head hidden (fp16)
__device__ __half g_U [(size_t)MROWS * 2048];  // projected gates (fp16)
__device__ __half g_x [(size_t)MROWS * EE];    // layer activations (fp16)
__device__ __half g_Wr [(size_t)LL * 2 * 1024 * EE]; // transposed+rounded sru_W: [l,d][n,k]
__device__ __half g_W1r[(size_t)EE * EE];            // transposed+rounded W1: [n,k]

// ---------------- helpers ----------------
__device__ __forceinline__ uint32_t su32(const void* p) {
    return (uint32_t)__cvta_generic_to_shared(p);
}

__device__ __forceinline__ void cp16(uint32_t dst, const void* src, int sz) {
    asm volatile("cp.async.ca.shared.global [%0], [%1], 16, %2;" :: "r"(dst), "l"(src), "r"(sz));
}

__device__ __forceinline__ void mma_f16(float c[4], const uint32_t a[4], const uint32_t b[2]) {
    asm volatile(
        "mma.sync.aligned.m16n8k16.row.col.f32.f16.f16.f32 "
        "{%0,%1,%2,%3}, {%4,%5,%6,%7}, {%8,%9}, {%0,%1,%2,%3};\n"
        : "+f"(c[0]), "+f"(c[1]), "+f"(c[2]), "+f"(c[3])
        : "r"(a[0]), "r"(a[1]), "r"(a[2]), "r"(a[3]), "r"(b[0]), "r"(b[1]));
}

__device__ __forceinline__ void ldsm4(uint32_t& r0, uint32_t& r1, uint32_t& r2, uint32_t& r3,
                                      uint32_t addr) {
    asm volatile("ldmatrix.sync.aligned.m8n8.x4.shared.b16 {%0,%1,%2,%3}, [%4];"
                 : "=r"(r0), "=r"(r1), "=r"(r2), "=r"(r3) : "r"(addr));
}

// ---------------- transpose + fp16 round: [K,N] -> [N,K] per batch ----------------
__global__ void __launch_bounds__(256) transpose_half(
    const float* __restrict__ in, __half* __restrict__ out, int K, int N)
{
    __shared__ float tile[32][33];
    int b = blockIdx.z;
    const float* ip = in + (size_t)b * K * N;
    __half* op = out + (size_t)b * K * N;
    int k0 = blockIdx.y * 32, n0 = blockIdx.x * 32;
    int tx = threadIdx.x & 31, ty = threadIdx.x >> 5;  // 32x8
#pragma unroll
    for (int i = 0; i < 32; i += 8)
        tile[ty + i][tx] = ip[(size_t)(k0 + ty + i) * N + n0 + tx];
    __syncthreads();
#pragma unroll
    for (int i = 0; i < 32; i += 8)
        op[(size_t)(n0 + ty + i) * K + k0 + tx] = __float2half_rn(tile[tx][ty + i]);
}

// ---------------- LayerNorm (fp32 input, fp16 output): one warp per token ----------------
__global__ void __launch_bounds__(256) ln_f32(
    const float* __restrict__ x, const float* __restrict__ g,
    const float* __restrict__ b, __half* __restrict__ out, int Mrows)
{
    int warp = (blockIdx.x * blockDim.x + threadIdx.x) >> 5;
    int lane = threadIdx.x & 31;
    if (warp >= Mrows) return;

    const float4* xr = (const float4*)(x + (size_t)warp * EE);
    float4 v[4];
    float s = 0.f, sq = 0.f;
#pragma unroll
    for (int j = 0; j < 4; j++) {
        v[j] = xr[lane + j * 32];
        s  += v[j].x + v[j].y + v[j].z + v[j].w;
        sq += v[j].x*v[j].x + v[j].y*v[j].y + v[j].z*v[j].z + v[j].w*v[j].w;
    }
#pragma unroll
    for (int o = 16; o > 0; o >>= 1) {
        s  += __shfl_xor_sync(0xffffffffu, s, o);
        sq += __shfl_xor_sync(0xffffffffu, sq, o);
    }
    float mean = s * (1.f / EE);
    float var  = sq * (1.f / EE) - mean * mean;
    float rstd = rsqrtf(var + 1e-5f);

    __half2* orow = (__half2*)(out + (size_t)warp * EE);
    const float4* gg4 = (const float4*)g;
    const float4* bb4 = (const float4*)b;
#pragma unroll
    for (int j = 0; j < 4; j++) {
        int e4 = lane + j * 32;
        float4 gg = gg4[e4], bb = bb4[e4];
        float w0 = (v[j].x - mean) * rstd * gg.x + bb.x;
        float w1 = (v[j].y - mean) * rstd * gg.y + bb.y;
        float w2 = (v[j].z - mean) * rstd * gg.z + bb.z;
        float w3 = (v[j].w - mean) * rstd * gg.w + bb.w;
        orow[e4 * 2 + 0] = __floats2half2_rn(w0, w1);
        orow[e4 * 2 + 1] = __floats2half2_rn(w2, w3);
    }
}

// ---------------- LayerNorm (fp16 input, fp16 output) ----------------
__global__ void __launch_bounds__(256) ln_f16(
    const __half* __restrict__ x, const float* __restrict__ g,
    const float* __restrict__ b, __half* __restrict__ out, int Mrows)
{
    int warp = (blockIdx.x * blockDim.x + threadIdx.x) >> 5;
    int lane = threadIdx.x & 31;
    if (warp >= Mrows) return;

    const uint4* xr = (const uint4*)(x + (size_t)warp * EE);  // 8 halves per uint4
    uint4 v[2];
    float f[16];
    float s = 0.f, sq = 0.f;
#pragma unroll
    for (int j = 0; j < 2; j++) {
        v[j] = xr[lane + j * 32];
        const __half2* h2 = (const __half2*)&v[j];
#pragma unroll
        for (int q = 0; q < 4; q++) {
            float2 p = __half22float2(h2[q]);
            f[j * 8 + q * 2 + 0] = p.x;
            f[j * 8 + q * 2 + 1] = p.y;
            s += p.x + p.y;
            sq += p.x * p.x + p.y * p.y;
        }
    }
#pragma unroll
    for (int o = 16; o > 0; o >>= 1) {
        s  += __shfl_xor_sync(0xffffffffu, s, o);
        sq += __shfl_xor_sync(0xffffffffu, sq, o);
    }
    float mean = s * (1.f / EE);
    float var  = sq * (1.f / EE) - mean * mean;
    float rstd = rsqrtf(var + 1e-5f);

    uint4* orow = (uint4*)(out + (size_t)warp * EE);
#pragma unroll
    for (int j = 0; j < 2; j++) {
        int e0 = (lane + j * 32) * 8;
        uint4 w;
        __half2* wh = (__half2*)&w;
#pragma unroll
        for (int q = 0; q < 4; q++) {
            int e = e0 + q * 2;
            float a0 = (f[j * 8 + q * 2 + 0] - mean) * rstd * g[e + 0] + b[e + 0];
            float a1 = (f[j * 8 + q * 2 + 1] - mean) * rstd * g[e + 1] + b[e + 1];
            wh[q] = __floats2half2_rn(a0, a1);
        }
        orow[lane + j * 32] = w;
    }
}

// ---------------- fp16 GEMM: C[M,N] = A[M,512] * Bt[N,512]^T, mma.sync m16n8k16 ----------------
// Tile 128x256x32, 4-stage cp.async pipeline, fragment double-buffering:
// every LDSM burst overlaps an MMA burst; one barrier per chunk.
// SW64-swizzled 64B rows: 16B chunk c stored at c ^ ((row>>1)&3).
#define BM 128
#define BN 256
#define BK 32
#define A_BYT (BM*64)                // 8192
#define B_BYT (BN*64)                // 16384
#define STG_BYT (A_BYT + B_BYT)      // 24576
#define NSTG 4
#define GEMM_SMEM (NSTG*STG_BYT + 128)

__global__ void __launch_bounds__(256, 1) gemm_fp16(
    const __half* __restrict__ A, const __half* __restrict__ Bt,
    const float* __restrict__ bias, __half* __restrict__ C,
    int Mrows, int Ncols, int dlog2, long long dstride)
{
    extern __shared__ __half smh[];
    const uint32_t ub = (su32(smh) + 127u) & ~127u;   // 128B-aligned smem base

    const int tid  = threadIdx.x;
    const int warp = tid >> 5, lane = tid & 31;
    const int g = lane >> 2, t = lane & 3;
    const int wm0 = (warp >> 2) * 64;   // 2 warps along M
    const int wn0 = (warp & 3) * 64;    // 4 warps along N
    const int m0 = blockIdx.y * BM;
    const int n0 = blockIdx.x * BN;
    const int dir = n0 >> dlog2;
    const int ncb = n0 & ((1 << dlog2) - 1);
    const __half* Bbase = Bt + (size_t)dir * dstride + (size_t)ncb * EE;

    // fill coords: row = tid>>2 (+64 per pass), swizzled 16B chunk
    const int frow = tid >> 2;
    const uint32_t fsw16 = (uint32_t)(((tid & 3) ^ ((frow >> 1) & 3)) * 16);
    const int fcol = (tid & 3) * 8;    // source col in halves

    // ldmatrix per-lane swizzled byte offsets (kk=0); kk=16 -> XOR 32
    const int ar = lane & 15;
    const uint32_t a_lane = (uint32_t)(ar * 64 + (((lane >> 4) ^ ((ar >> 1) & 3)) * 16));
    const int br = (lane & 7) | (((lane >> 4) & 1) << 3);
    const uint32_t b_lane = (uint32_t)(br * 64 + ((((lane >> 3) & 1) ^ ((br >> 1) & 3)) * 16));

    float acc[4][8][4];
#pragma unroll
    for (int i = 0; i < 4; i++)
#pragma unroll
        for (int j = 0; j < 8; j++)
#pragma unroll
            for (int k = 0; k < 4; k++) acc[i][j][k] = 0.f;

    auto fill = [&](int kt, int s) {
        uint32_t Ast = ub + s * STG_BYT;
        uint32_t Bst = Ast + A_BYT;
        const int k0 = kt * BK + fcol;
#pragma unroll
        for (int i = 0; i < 2; i++) {
            int r = frow + i * 64;
            int m = m0 + r;
            bool ok = (m < Mrows);
            cp16(Ast + (uint32_t)(r * 64) + fsw16,
                 A + (size_t)(ok ? m : 0) * EE + k0, ok ? 16 : 0);
        }
#pragma unroll
        for (int i = 0; i < 4; i++) {
            int r = frow + i * 64;
            cp16(Bst + (uint32_t)(r * 64) + fsw16, Bbase + (size_t)r * EE + k0, 16);
        }
    };

    // fragment double buffers
    uint32_t afA[4][4], bfA[8][2], afB[4][4], bfB[8][2];

    auto ldsm_frags = [&](int s, int ks, uint32_t af[4][4], uint32_t bf[8][2]) {
        const uint32_t kx = ks ? 32u : 0u;
        const uint32_t a_base = ub + s * STG_BYT + a_lane;
        const uint32_t b_base = ub + s * STG_BYT + A_BYT + b_lane;
#pragma unroll
        for (int i = 0; i < 4; i++)
            ldsm4(af[i][0], af[i][1], af[i][2], af[i][3],
                  (a_base + (uint32_t)((wm0 + i * 16) * 64)) ^ kx);
#pragma unroll
        for (int jp = 0; jp < 4; jp++) {
            int j = jp * 2;
            ldsm4(bf[j][0], bf[j][1], bf[j + 1][0], bf[j + 1][1],
                  (b_base + (uint32_t)((wn0 + j * 8) * 64)) ^ kx);
        }
    };

    auto do_mma = [&](uint32_t af[4][4], uint32_t bf[8][2]) {
#pragma unroll
        for (int i = 0; i < 4; i++)
#pragma unroll
            for (int j = 0; j < 8; j++)
                mma_f16(acc[i][j], af[i], bf[j]);
    };

    const int NKT = EE / BK;  // 16

    fill(0, 0); asm volatile("cp.async.commit_group;");
    fill(1, 1); asm volatile("cp.async.commit_group;");
    fill(2, 2); asm volatile("cp.async.commit_group;");
    asm volatile("cp.async.wait_group 2;");
    __syncthreads();
    ldsm_frags(0, 0, afA, bfA);

    for (int c = 0; c < NKT; c++) {
        const int s = c & 3;
        ldsm_frags(s, 1, afB, bfB);       // overlaps mma below
        do_mma(afA, bfA);
        asm volatile("cp.async.wait_group 1;");  // stage c+1 groups complete
        __syncthreads();                         // visibility + safe overwrite of stage c-1
        if (c + 3 < NKT) fill(c + 3, (c + 3) & 3);
        asm volatile("cp.async.commit_group;");
        if (c + 1 < NKT) ldsm_frags((c + 1) & 3, 0, afA, bfA);  // overlaps mma below
        do_mma(afB, bfB);
    }

    // epilogue: fp32 acc (+bias) -> fp16 stores
#pragma unroll
    for (int i = 0; i < 4; i++) {
        int r0 = m0 + wm0 + i * 16 + g;
        int r1 = r0 + 8;
#pragma unroll
        for (int j = 0; j < 8; j++) {
            int cc = n0 + wn0 + j * 8 + 2 * t;
            float b0v = 0.f, b1v = 0.f;
            if (bias) { b0v = bias[cc]; b1v = bias[cc + 1]; }
            if (r0 < Mrows)
                *(__half2*)(C + (size_t)r0 * Ncols + cc) =
                    __floats2half2_rn(acc[i][j][0] + b0v, acc[i][j][1] + b1v);
            if (r1 < Mrows)
                *(__half2*)(C + (size_t)r1 * Ncols + cc) =
                    __floats2half2_rn(acc[i][j][2] + b0v, acc[i][j][3] + b1v);
        }
    }
}

// ---------------- SRU elementwise scan (fp16 U in, fp16 X out) ----------------
__global__ void __launch_bounds__(256) sru_scan(
    const __half* __restrict__ U, const float* __restrict__ v,
    const float* __restrict__ bp, __half* __restrict__ X)
{
    int tid = blockIdx.x * blockDim.x + threadIdx.x;
    if (tid >= 2 * BB * DD) return;
    int dir = tid / (BB * DD);
    int rem = tid - dir * (BB * DD);
    int b = rem / DD;
    int dd = rem - b * DD;

    float vf = v[dir * 2 * DD + dd];
    float vr = v[dir * 2 * DD + DD + dd];
    float bf = bp[dir * 2 * DD + dd];
    float br = bp[dir * 2 * DD + DD + dd];

    const size_t colU = (size_t)dir * 1024 + dd;
    const size_t colX = (size_t)dir * DD + dd;

    float c = 0.f;
    for (int s = 0; s < TT; s++) {
        int t = dir ? (TT - 1 - s) : s;
        const __half* up = U + ((size_t)t * BB + b) * 2048 + colU;
        float u0 = __half2float(up[0]);
        float u1 = __half2float(up[256]);
        float u2 = __half2float(up[512]);
        float u3 = __half2float(up[768]);
        float f = 1.f / (1.f + expf(-(u1 + vf * c + bf)));
        c = f * c + (1.f - f) * u0;
        float r = 1.f / (1.f + expf(-(u2 + vr * c + br)));
        X[((size_t)t * BB + b) * EE + colX] = __float2half_rn(r * c + (1.f - r) * u3);
    }
}

// ---------------- head: BN(eval) + relu + W2 (512x4) + log_softmax; one warp per token ----------------
__global__ void __launch_bounds__(256) head_kernel(
    const __half* __restrict__ h,
    const float* __restrict__ bn_g, const float* __restrict__ bn_b,
    const float* __restrict__ bn_mean, const float* __restrict__ bn_var,
    const float* __restrict__ W2, const float* __restrict__ b2,
    float* __restrict__ out, int Mrows)
{
    __shared__ float w2s[EE * 4];
    __shared__ float scs[EE], tbs[EE];
    __shared__ float b2s[4];
    int tid = threadIdx.x;
    for (int i = tid; i < EE * 4; i += 256) w2s[i] = W2[i];
    for (int i = tid; i < EE; i += 256) {
        float s = bn_g[i] * rsqrtf(bn_var[i] + 1e-5f);
        scs[i] = s;
        tbs[i] = bn_b[i] - bn_mean[i] * s;
    }
    if (tid < 4) b2s[tid] = b2[tid];
    __syncthreads();

    int warp = (blockIdx.x * blockDim.x + tid) >> 5;
    int lane = tid & 31;
    if (warp >= Mrows) return;

    const uint4* hr = (const uint4*)(h + (size_t)warp * EE);  // 8 halves per uint4
    float a0 = 0.f, a1 = 0.f, a2 = 0.f, a3 = 0.f;
#pragma unroll
    for (int j = 0; j < 2; j++) {
        uint4 hv = hr[lane + j * 32];
        const __half2* h2 = (const __half2*)&hv;
        int e0 = (lane + j * 32) * 8;
#pragma unroll
        for (int q = 0; q < 4; q++) {
            float2 p = __half22float2(h2[q]);
            int e = e0 + q * 2;
            float v0 = fmaxf(p.x * scs[e]     + tbs[e],     0.f);
            float v1 = fmaxf(p.y * scs[e + 1] + tbs[e + 1], 0.f);
            a0 += v0 * w2s[e * 4 + 0] + v1 * w2s[(e + 1) * 4 + 0];
            a1 += v0 * w2s[e * 4 + 1] + v1 * w2s[(e + 1) * 4 + 1];
            a2 += v0 * w2s[e * 4 + 2] + v1 * w2s[(e + 1) * 4 + 2];
            a3 += v0 * w2s[e * 4 + 3] + v1 * w2s[(e + 1) * 4 + 3];
        }
    }
#pragma unroll
    for (int o = 16; o > 0; o >>= 1) {
        a0 += __shfl_xor_sync(0xffffffffu, a0, o);
        a1 += __shfl_xor_sync(0xffffffffu, a1, o);
        a2 += __shfl_xor_sync(0xffffffffu, a2, o);
        a3 += __shfl_xor_sync(0xffffffffu, a3, o);
    }
    if (lane == 0) {
        float l0 = a0 + b2s[0], l1 = a1 + b2s[1], l2 = a2 + b2s[2], l3 = a3 + b2s[3];
        float m = fmaxf(fmaxf(l0, l1), fmaxf(l2, l3));
        float se = expf(l0 - m) + expf(l1 - m) + expf(l2 - m) + expf(l3 - m);
        float lse = m + logf(se);
        float4 o = make_float4(l0 - lse, l1 - lse, l2 - lse, l3 - lse);
        ((float4*)out)[warp] = o;
    }
}

// ---------------- launch ----------------
extern "C" void kernel_launch(void* const* d_in, const int* in_sizes, int n_in,
                              void* d_out, int out_size)
{
    const float* sentence = (const float*)d_in[0];
    const float* sru_W    = (const float*)d_in[1];
    const float* sru_v    = (const float*)d_in[2];
    const float* sru_b    = (const float*)d_in[3];
    const float* ln_g     = (const float*)d_in[4];
    const float* ln_b     = (const float*)d_in[5];
    const float* W1       = (const float*)d_in[6];
    const float* b1       = (const float*)d_in[7];
    const float* bn_g     = (const float*)d_in[8];
    const float* bn_b     = (const float*)d_in[9];
    const float* bn_mean  = (const float*)d_in[10];
    const float* bn_var   = (const float*)d_in[11];
    const float* W2       = (const float*)d_in[12];
    const float* b2       = (const float*)d_in[13];
    float* out = (float*)d_out;

    __half *xl, *U, *x, *Wr, *W1r;
    cudaGetSymbolAddress((void**)&xl,  g_xl);
    cudaGetSymbolAddress((void**)&U,   g_U);
    cudaGetSymbolAddress((void**)&x,   g_x);
    cudaGetSymbolAddress((void**)&Wr,  g_Wr);
    cudaGetSymbolAddress((void**)&W1r, g_W1r);

    cudaFuncSetAttribute(gemm_fp16, cudaFuncAttributeMaxDynamicSharedMemorySize, GEMM_SMEM);

    const int M = MROWS;
    const int mtiles = (M + BM - 1) / BM;        // 782
    dim3 gemm_grid_layer(2048 / BN, mtiles);     // (8, 782)
    dim3 gemm_grid_head(EE / BN, mtiles);        // (2, 782)
    int ln_blocks = (M * 32 + 255) / 256;        // 12500
    int scan_blocks = (2 * BB * DD + 255) / 256; // 2000

    // transpose + fp16-round weights
    transpose_half<<<dim3(1024 / 32, EE / 32, LL * 2), 256>>>(sru_W, Wr, EE, 1024);
    transpose_half<<<dim3(EE / 32, EE / 32, 1), 256>>>(W1, W1r, EE, EE);

    for (int l = 0; l < LL; l++) {
        if (l == 0)
            ln_f32<<<ln_blocks, 256>>>(sentence, ln_g, ln_b, xl, M);
        else
            ln_f16<<<ln_blocks, 256>>>(x, ln_g + l * EE, ln_b + l * EE, xl, M);
        gemm_fp16<<<gemm_grid_layer, 256, GEMM_SMEM>>>(
            xl, Wr + (size_t)l * 2 * 1024 * EE, nullptr, U,
            M, 2048, 10, (long long)1024 * EE);
        sru_scan<<<scan_blocks, 256>>>(U, sru_v + l * 4 * DD, sru_b + l * 4 * DD, x);
    }
    // head GEMM: h = x @ W1 + b1 -> xl
    gemm_fp16<<<gemm_grid_head, 256, GEMM_SMEM>>>(
        x, W1r, b1, xl, M, EE, 30, 0LL);
    head_kernel<<<ln_blocks, 256>>>(xl, bn_g, bn_b, bn_mean, bn_var, W2, b2, out, M);
}

// round 14
// speedup vs baseline: 2.4362x; 1.0121x over previous
#include <cuda_runtime.h>
#include <cuda_fp16.h>
#include <cstdint>
#include <cmath>

// Problem constants
#define TT 100
#define BB 1000
#define EE 512
#define DD 256
#define LL 4
#define MROWS (TT*BB)          // 100000

// ---------------- scratch (static device memory; no allocations) ----------------
__device__ __half g_xl[(size_t)MROWS * EE];    // LN output / head hidden (fp16)
__device__ __half g_U [(size_t)MROWS * 2048];  // projected gates (fp16)
__device__ __half g_x [(size_t)MROWS * EE];    // layer activations (fp16)
__device__ __half g_Wr [(size_t)LL * 2 * 1024 * EE]; // transposed+rounded sru_W: [l,d][n,k]
__device__ __half g_W1r[(size_t)EE * EE];            // transposed+rounded W1: [n,k]

// ---------------- helpers ----------------
__device__ __forceinline__ uint32_t su32(const void* p) {
    return (uint32_t)__cvta_generic_to_shared(p);
}

__device__ __forceinline__ void cp16(uint32_t dst, const void* src, int sz) {
    asm volatile("cp.async.ca.shared.global [%0], [%1], 16, %2;" :: "r"(dst), "l"(src), "r"(sz));
}

__device__ __forceinline__ void mma_f16(float c[4], const uint32_t a[4], const uint32_t b[2]) {
    asm volatile(
        "mma.sync.aligned.m16n8k16.row.col.f32.f16.f16.f32 "
        "{%0,%1,%2,%3}, {%4,%5,%6,%7}, {%8,%9}, {%0,%1,%2,%3};\n"
        : "+f"(c[0]), "+f"(c[1]), "+f"(c[2]), "+f"(c[3])
        : "r"(a[0]), "r"(a[1]), "r"(a[2]), "r"(a[3]), "r"(b[0]), "r"(b[1]));
}

__device__ __forceinline__ void ldsm4(uint32_t& r0, uint32_t& r1, uint32_t& r2, uint32_t& r3,
                                      uint32_t addr) {
    asm volatile("ldmatrix.sync.aligned.m8n8.x4.shared.b16 {%0,%1,%2,%3}, [%4];"
                 : "=r"(r0), "=r"(r1), "=r"(r2), "=r"(r3) : "r"(addr));
}

// ---------------- transpose + fp16 round: [K,N] -> [N,K] per batch ----------------
__global__ void __launch_bounds__(256) transpose_half(
    const float* __restrict__ in, __half* __restrict__ out, int K, int N)
{
    __shared__ float tile[32][33];
    int b = blockIdx.z;
    const float* ip = in + (size_t)b * K * N;
    __half* op = out + (size_t)b * K * N;
    int k0 = blockIdx.y * 32, n0 = blockIdx.x * 32;
    int tx = threadIdx.x & 31, ty = threadIdx.x >> 5;  // 32x8
#pragma unroll
    for (int i = 0; i < 32; i += 8)
        tile[ty + i][tx] = ip[(size_t)(k0 + ty + i) * N + n0 + tx];
    __syncthreads();
#pragma unroll
    for (int i = 0; i < 32; i += 8)
        op[(size_t)(n0 + ty + i) * K + k0 + tx] = __float2half_rn(tile[tx][ty + i]);
}

// ---------------- LayerNorm (fp32 input, fp16 output): one warp per token ----------------
__global__ void __launch_bounds__(256) ln_f32(
    const float* __restrict__ x, const float* __restrict__ g,
    const float* __restrict__ b, __half* __restrict__ out, int Mrows)
{
    int warp = (blockIdx.x * blockDim.x + threadIdx.x) >> 5;
    int lane = threadIdx.x & 31;
    if (warp >= Mrows) return;

    const float4* xr = (const float4*)(x + (size_t)warp * EE);
    float4 v[4];
    float s = 0.f, sq = 0.f;
#pragma unroll
    for (int j = 0; j < 4; j++) {
        v[j] = xr[lane + j * 32];
        s  += v[j].x + v[j].y + v[j].z + v[j].w;
        sq += v[j].x*v[j].x + v[j].y*v[j].y + v[j].z*v[j].z + v[j].w*v[j].w;
    }
#pragma unroll
    for (int o = 16; o > 0; o >>= 1) {
        s  += __shfl_xor_sync(0xffffffffu, s, o);
        sq += __shfl_xor_sync(0xffffffffu, sq, o);
    }
    float mean = s * (1.f / EE);
    float var  = sq * (1.f / EE) - mean * mean;
    float rstd = rsqrtf(var + 1e-5f);

    __half2* orow = (__half2*)(out + (size_t)warp * EE);
    const float4* gg4 = (const float4*)g;
    const float4* bb4 = (const float4*)b;
#pragma unroll
    for (int j = 0; j < 4; j++) {
        int e4 = lane + j * 32;
        float4 gg = gg4[e4], bb = bb4[e4];
        float w0 = (v[j].x - mean) * rstd * gg.x + bb.x;
        float w1 = (v[j].y - mean) * rstd * gg.y + bb.y;
        float w2 = (v[j].z - mean) * rstd * gg.z + bb.z;
        float w3 = (v[j].w - mean) * rstd * gg.w + bb.w;
        orow[e4 * 2 + 0] = __floats2half2_rn(w0, w1);
        orow[e4 * 2 + 1] = __floats2half2_rn(w2, w3);
    }
}

// ---------------- LayerNorm (fp16 input, fp16 output) ----------------
__global__ void __launch_bounds__(256) ln_f16(
    const __half* __restrict__ x, const float* __restrict__ g,
    const float* __restrict__ b, __half* __restrict__ out, int Mrows)
{
    int warp = (blockIdx.x * blockDim.x + threadIdx.x) >> 5;
    int lane = threadIdx.x & 31;
    if (warp >= Mrows) return;

    const uint4* xr = (const uint4*)(x + (size_t)warp * EE);  // 8 halves per uint4
    uint4 v[2];
    float f[16];
    float s = 0.f, sq = 0.f;
#pragma unroll
    for (int j = 0; j < 2; j++) {
        v[j] = xr[lane + j * 32];
        const __half2* h2 = (const __half2*)&v[j];
#pragma unroll
        for (int q = 0; q < 4; q++) {
            float2 p = __half22float2(h2[q]);
            f[j * 8 + q * 2 + 0] = p.x;
            f[j * 8 + q * 2 + 1] = p.y;
            s += p.x + p.y;
            sq += p.x * p.x + p.y * p.y;
        }
    }
#pragma unroll
    for (int o = 16; o > 0; o >>= 1) {
        s  += __shfl_xor_sync(0xffffffffu, s, o);
        sq += __shfl_xor_sync(0xffffffffu, sq, o);
    }
    float mean = s * (1.f / EE);
    float var  = sq * (1.f / EE) - mean * mean;
    float rstd = rsqrtf(var + 1e-5f);

    uint4* orow = (uint4*)(out + (size_t)warp * EE);
#pragma unroll
    for (int j = 0; j < 2; j++) {
        int e0 = (lane + j * 32) * 8;
        uint4 w;
        __half2* wh = (__half2*)&w;
#pragma unroll
        for (int q = 0; q < 4; q++) {
            int e = e0 + q * 2;
            float a0 = (f[j * 8 + q * 2 + 0] - mean) * rstd * g[e + 0] + b[e + 0];
            float a1 = (f[j * 8 + q * 2 + 1] - mean) * rstd * g[e + 1] + b[e + 1];
            wh[q] = __floats2half2_rn(a0, a1);
        }
        orow[lane + j * 32] = w;
    }
}

// ---------------- fp16 GEMM: C[M,N] = A[M,512] * Bt[N,512]^T, mma.sync m16n8k16 ----------------
// Tile 128x128x32, 128-thread CTA (2x2 warps, warp tile 64x64), 2 CTAs/SM.
// 4-stage cp.async pipeline + fragment double-buffering; one barrier per chunk.
// SW64-swizzled 64B rows: 16B chunk c stored at c ^ ((row>>1)&3).
#define BM 128
#define BN 128
#define BK 32
#define A_BYT (BM*64)                // 8192
#define B_BYT (BN*64)                // 8192
#define STG_BYT (A_BYT + B_BYT)      // 16384
#define NSTG 4
#define GEMM_SMEM (NSTG*STG_BYT + 128)

__global__ void __launch_bounds__(128, 2) gemm_fp16(
    const __half* __restrict__ A, const __half* __restrict__ Bt,
    const float* __restrict__ bias, __half* __restrict__ C,
    int Mrows, int Ncols, int dlog2, long long dstride)
{
    extern __shared__ __half smh[];
    const uint32_t ub = (su32(smh) + 127u) & ~127u;   // 128B-aligned smem base

    const int tid  = threadIdx.x;
    const int warp = tid >> 5, lane = tid & 31;
    const int g = lane >> 2, t = lane & 3;
    const int wm0 = (warp >> 1) * 64;   // 2 warps along M
    const int wn0 = (warp & 1) * 64;    // 2 warps along N
    const int m0 = blockIdx.y * BM;
    const int n0 = blockIdx.x * BN;
    const int dir = n0 >> dlog2;
    const int ncb = n0 & ((1 << dlog2) - 1);
    const __half* Bbase = Bt + (size_t)dir * dstride + (size_t)ncb * EE;

    // fill coords: row = tid>>2 (+32 per pass), swizzled 16B chunk
    const int frow = tid >> 2;
    const uint32_t fsw16 = (uint32_t)(((tid & 3) ^ ((frow >> 1) & 3)) * 16);
    const int fcol = (tid & 3) * 8;    // source col in halves

    // ldmatrix per-lane swizzled byte offsets (kk=0); kk=16 -> XOR 32
    const int ar = lane & 15;
    const uint32_t a_lane = (uint32_t)(ar * 64 + (((lane >> 4) ^ ((ar >> 1) & 3)) * 16));
    const int br = (lane & 7) | (((lane >> 4) & 1) << 3);
    const uint32_t b_lane = (uint32_t)(br * 64 + ((((lane >> 3) & 1) ^ ((br >> 1) & 3)) * 16));

    float acc[4][8][4];
#pragma unroll
    for (int i = 0; i < 4; i++)
#pragma unroll
        for (int j = 0; j < 8; j++)
#pragma unroll
            for (int k = 0; k < 4; k++) acc[i][j][k] = 0.f;

    auto fill = [&](int kt, int s) {
        uint32_t Ast = ub + s * STG_BYT;
        uint32_t Bst = Ast + A_BYT;
        const int k0 = kt * BK + fcol;
#pragma unroll
        for (int i = 0; i < 4; i++) {
            int r = frow + i * 32;
            int m = m0 + r;
            bool ok = (m < Mrows);
            cp16(Ast + (uint32_t)(r * 64) + fsw16,
                 A + (size_t)(ok ? m : 0) * EE + k0, ok ? 16 : 0);
        }
#pragma unroll
        for (int i = 0; i < 4; i++) {
            int r = frow + i * 32;
            cp16(Bst + (uint32_t)(r * 64) + fsw16, Bbase + (size_t)r * EE + k0, 16);
        }
    };

    // fragment double buffers
    uint32_t afA[4][4], bfA[8][2], afB[4][4], bfB[8][2];

    auto ldsm_frags = [&](int s, int ks, uint32_t af[4][4], uint32_t bf[8][2]) {
        const uint32_t kx = ks ? 32u : 0u;
        const uint32_t a_base = ub + s * STG_BYT + a_lane;
        const uint32_t b_base = ub + s * STG_BYT + A_BYT + b_lane;
#pragma unroll
        for (int i = 0; i < 4; i++)
            ldsm4(af[i][0], af[i][1], af[i][2], af[i][3],
                  (a_base + (uint32_t)((wm0 + i * 16) * 64)) ^ kx);
#pragma unroll
        for (int jp = 0; jp < 4; jp++) {
            int j = jp * 2;
            ldsm4(bf[j][0], bf[j][1], bf[j + 1][0], bf[j + 1][1],
                  (b_base + (uint32_t)((wn0 + j * 8) * 64)) ^ kx);
        }
    };

    auto do_mma = [&](uint32_t af[4][4], uint32_t bf[8][2]) {
#pragma unroll
        for (int i = 0; i < 4; i++)
#pragma unroll
            for (int j = 0; j < 8; j++)
                mma_f16(acc[i][j], af[i], bf[j]);
    };

    const int NKT = EE / BK;  // 16

    fill(0, 0); asm volatile("cp.async.commit_group;");
    fill(1, 1); asm volatile("cp.async.commit_group;");
    fill(2, 2); asm volatile("cp.async.commit_group;");
    asm volatile("cp.async.wait_group 2;");
    __syncthreads();
    ldsm_frags(0, 0, afA, bfA);

    for (int c = 0; c < NKT; c++) {
        const int s = c & 3;
        ldsm_frags(s, 1, afB, bfB);       // overlaps mma below
        do_mma(afA, bfA);
        asm volatile("cp.async.wait_group 1;");  // stage c+1 groups complete
        __syncthreads();                         // visibility + safe overwrite of stage c-1
        if (c + 3 < NKT) fill(c + 3, (c + 3) & 3);
        asm volatile("cp.async.commit_group;");
        if (c + 1 < NKT) ldsm_frags((c + 1) & 3, 0, afA, bfA);  // overlaps mma below
        do_mma(afB, bfB);
    }

    // epilogue: fp32 acc (+bias) -> fp16 stores
#pragma unroll
    for (int i = 0; i < 4; i++) {
        int r0 = m0 + wm0 + i * 16 + g;
        int r1 = r0 + 8;
#pragma unroll
        for (int j = 0; j < 8; j++) {
            int cc = n0 + wn0 + j * 8 + 2 * t;
            float b0v = 0.f, b1v = 0.f;
            if (bias) { b0v = bias[cc]; b1v = bias[cc + 1]; }
            if (r0 < Mrows)
                *(__half2*)(C + (size_t)r0 * Ncols + cc) =
                    __floats2half2_rn(acc[i][j][0] + b0v, acc[i][j][1] + b1v);
            if (r1 < Mrows)
                *(__half2*)(C + (size_t)r1 * Ncols + cc) =
                    __floats2half2_rn(acc[i][j][2] + b0v, acc[i][j][3] + b1v);
        }
    }
}

// ---------------- SRU elementwise scan (fp16 U in, fp16 X out) ----------------
__global__ void __launch_bounds__(256) sru_scan(
    const __half* __restrict__ U, const float* __restrict__ v,
    const float* __restrict__ bp, __half* __restrict__ X)
{
    int tid = blockIdx.x * blockDim.x + threadIdx.x;
    if (tid >= 2 * BB * DD) return;
    int dir = tid / (BB * DD);
    int rem = tid - dir * (BB * DD);
    int b = rem / DD;
    int dd = rem - b * DD;

    float vf = v[dir * 2 * DD + dd];
    float vr = v[dir * 2 * DD + DD + dd];
    float bf = bp[dir * 2 * DD + dd];
    float br = bp[dir * 2 * DD + DD + dd];

    const size_t colU = (size_t)dir * 1024 + dd;
    const size_t colX = (size_t)dir * DD + dd;

    float c = 0.f;
    for (int s = 0; s < TT; s++) {
        int t = dir ? (TT - 1 - s) : s;
        const __half* up = U + ((size_t)t * BB + b) * 2048 + colU;
        float u0 = __half2float(up[0]);
        float u1 = __half2float(up[256]);
        float u2 = __half2float(up[512]);
        float u3 = __half2float(up[768]);
        float f = 1.f / (1.f + expf(-(u1 + vf * c + bf)));
        c = f * c + (1.f - f) * u0;
        float r = 1.f / (1.f + expf(-(u2 + vr * c + br)));
        X[((size_t)t * BB + b) * EE + colX] = __float2half_rn(r * c + (1.f - r) * u3);
    }
}

// ---------------- head: BN(eval) + relu + W2 (512x4) + log_softmax; one warp per token ----------------
__global__ void __launch_bounds__(256) head_kernel(
    const __half* __restrict__ h,
    const float* __restrict__ bn_g, const float* __restrict__ bn_b,
    const float* __restrict__ bn_mean, const float* __restrict__ bn_var,
    const float* __restrict__ W2, const float* __restrict__ b2,
    float* __restrict__ out, int Mrows)
{
    __shared__ float w2s[EE * 4];
    __shared__ float scs[EE], tbs[EE];
    __shared__ float b2s[4];
    int tid = threadIdx.x;
    for (int i = tid; i < EE * 4; i += 256) w2s[i] = W2[i];
    for (int i = tid; i < EE; i += 256) {
        float s = bn_g[i] * rsqrtf(bn_var[i] + 1e-5f);
        scs[i] = s;
        tbs[i] = bn_b[i] - bn_mean[i] * s;
    }
    if (tid < 4) b2s[tid] = b2[tid];
    __syncthreads();

    int warp = (blockIdx.x * blockDim.x + tid) >> 5;
    int lane = tid & 31;
    if (warp >= Mrows) return;

    const uint4* hr = (const uint4*)(h + (size_t)warp * EE);  // 8 halves per uint4
    float a0 = 0.f, a1 = 0.f, a2 = 0.f, a3 = 0.f;
#pragma unroll
    for (int j = 0; j < 2; j++) {
        uint4 hv = hr[lane + j * 32];
        const __half2* h2 = (const __half2*)&hv;
        int e0 = (lane + j * 32) * 8;
#pragma unroll
        for (int q = 0; q < 4; q++) {
            float2 p = __half22float2(h2[q]);
            int e = e0 + q * 2;
            float v0 = fmaxf(p.x * scs[e]     + tbs[e],     0.f);
            float v1 = fmaxf(p.y * scs[e + 1] + tbs[e + 1], 0.f);
            a0 += v0 * w2s[e * 4 + 0] + v1 * w2s[(e + 1) * 4 + 0];
            a1 += v0 * w2s[e * 4 + 1] + v1 * w2s[(e + 1) * 4 + 1];
            a2 += v0 * w2s[e * 4 + 2] + v1 * w2s[(e + 1) * 4 + 2];
            a3 += v0 * w2s[e * 4 + 3] + v1 * w2s[(e + 1) * 4 + 3];
        }
    }
#pragma unroll
    for (int o = 16; o > 0; o >>= 1) {
        a0 += __shfl_xor_sync(0xffffffffu, a0, o);
        a1 += __shfl_xor_sync(0xffffffffu, a1, o);
        a2 += __shfl_xor_sync(0xffffffffu, a2, o);
        a3 += __shfl_xor_sync(0xffffffffu, a3, o);
    }
    if (lane == 0) {
        float l0 = a0 + b2s[0], l1 = a1 + b2s[1], l2 = a2 + b2s[2], l3 = a3 + b2s[3];
        float m = fmaxf(fmaxf(l0, l1), fmaxf(l2, l3));
        float se = expf(l0 - m) + expf(l1 - m) + expf(l2 - m) + expf(l3 - m);
        float lse = m + logf(se);
        float4 o = make_float4(l0 - lse, l1 - lse, l2 - lse, l3 - lse);
        ((float4*)out)[warp] = o;
    }
}

// ---------------- launch ----------------
extern "C" void kernel_launch(void* const* d_in, const int* in_sizes, int n_in,
                              void* d_out, int out_size)
{
    const float* sentence = (const float*)d_in[0];
    const float* sru_W    = (const float*)d_in[1];
    const float* sru_v    = (const float*)d_in[2];
    const float* sru_b    = (const float*)d_in[3];
    const float* ln_g     = (const float*)d_in[4];
    const float* ln_b     = (const float*)d_in[5];
    const float* W1       = (const float*)d_in[6];
    const float* b1       = (const float*)d_in[7];
    const float* bn_g     = (const float*)d_in[8];
    const float* bn_b     = (const float*)d_in[9];
    const float* bn_mean  = (const float*)d_in[10];
    const float* bn_var   = (const float*)d_in[11];
    const float* W2       = (const float*)d_in[12];
    const float* b2       = (const float*)d_in[13];
    float* out = (float*)d_out;

    __half *xl, *U, *x, *Wr, *W1r;
    cudaGetSymbolAddress((void**)&xl,  g_xl);
    cudaGetSymbolAddress((void**)&U,   g_U);
    cudaGetSymbolAddress((void**)&x,   g_x);
    cudaGetSymbolAddress((void**)&Wr,  g_Wr);
    cudaGetSymbolAddress((void**)&W1r, g_W1r);

    cudaFuncSetAttribute(gemm_fp16, cudaFuncAttributeMaxDynamicSharedMemorySize, GEMM_SMEM);

    const int M = MROWS;
    const int mtiles = (M + BM - 1) / BM;        // 782
    dim3 gemm_grid_layer(2048 / BN, mtiles);     // (16, 782)
    dim3 gemm_grid_head(EE / BN, mtiles);        // (4, 782)
    int ln_blocks = (M * 32 + 255) / 256;        // 12500
    int scan_blocks = (2 * BB * DD + 255) / 256; // 2000

    // transpose + fp16-round weights
    transpose_half<<<dim3(1024 / 32, EE / 32, LL * 2), 256>>>(sru_W, Wr, EE, 1024);
    transpose_half<<<dim3(EE / 32, EE / 32, 1), 256>>>(W1, W1r, EE, EE);

    for (int l = 0; l < LL; l++) {
        if (l == 0)
            ln_f32<<<ln_blocks, 256>>>(sentence, ln_g, ln_b, xl, M);
        else
            ln_f16<<<ln_blocks, 256>>>(x, ln_g + l * EE, ln_b + l * EE, xl, M);
        gemm_fp16<<<gemm_grid_layer, 128, GEMM_SMEM>>>(
            xl, Wr + (size_t)l * 2 * 1024 * EE, nullptr, U,
            M, 2048, 10, (long long)1024 * EE);
        sru_scan<<<scan_blocks, 256>>>(U, sru_v + l * 4 * DD, sru_b + l * 4 * DD, x);
    }
    // head GEMM: h = x @ W1 + b1 -> xl
    gemm_fp16<<<gemm_grid_head, 128, GEMM_SMEM>>>(
        x, W1r, b1, xl, M, EE, 30, 0LL);
    head_kernel<<<ln_blocks, 256>>>(xl, bn_g, bn_b, bn_mean, bn_var, W2, b2, out, M);
}

// round 16
// speedup vs baseline: 2.4495x; 1.0055x over previous
#include <cuda_runtime.h>
#include <cuda_fp16.h>
#include <cstdint>
#include <cmath>

// Problem constants
#define TT 100
#define BB 1000
#define EE 512
#define DD 256
#define LL 4
#define MROWS (TT*BB)          // 100000

// ---------------- scratch (static device memory; no allocations) ----------------
__device__ __half g_xl[(size_t)MROWS * EE];    // LN output / head hidden (fp16)
__device__ __half g_U [(size_t)MROWS * 2048];  // projected gates (fp16, gate-interleaved)
__device__ __half g_x [(size_t)MROWS * EE];    // layer activations (fp16)
__device__ __half g_Wr [(size_t)LL * 2 * 1024 * EE]; // transposed+rounded sru_W: [l,d][n',k], n'=dd*4+gate
__device__ __half g_W1r[(size_t)EE * EE];            // transposed+rounded W1: [n,k]

// ---------------- helpers ----------------
__device__ __forceinline__ uint32_t su32(const void* p) {
    return (uint32_t)__cvta_generic_to_shared(p);
}

__device__ __forceinline__ void cp16(uint32_t dst, const void* src, int sz) {
    asm volatile("cp.async.ca.shared.global [%0], [%1], 16, %2;" :: "r"(dst), "l"(src), "r"(sz));
}

__device__ __forceinline__ void mma_f16(float c[4], const uint32_t a[4], const uint32_t b[2]) {
    asm volatile(
        "mma.sync.aligned.m16n8k16.row.col.f32.f16.f16.f32 "
        "{%0,%1,%2,%3}, {%4,%5,%6,%7}, {%8,%9}, {%0,%1,%2,%3};\n"
        : "+f"(c[0]), "+f"(c[1]), "+f"(c[2]), "+f"(c[3])
        : "r"(a[0]), "r"(a[1]), "r"(a[2]), "r"(a[3]), "r"(b[0]), "r"(b[1]));
}

__device__ __forceinline__ void ldsm4(uint32_t& r0, uint32_t& r1, uint32_t& r2, uint32_t& r3,
                                      uint32_t addr) {
    asm volatile("ldmatrix.sync.aligned.m8n8.x4.shared.b16 {%0,%1,%2,%3}, [%4];"
                 : "=r"(r0), "=r"(r1), "=r"(r2), "=r"(r3) : "r"(addr));
}

// ---------------- transpose + fp16 round: [K,N] -> [N,K] per batch ----------------
// perm=1: output row n' = (n&255)*4 + (n>>8)  (gate-interleave within 1024-col dir block)
__global__ void __launch_bounds__(256) transpose_half(
    const float* __restrict__ in, __half* __restrict__ out, int K, int N, int perm)
{
    __shared__ float tile[32][33];
    int b = blockIdx.z;
    const float* ip = in + (size_t)b * K * N;
    __half* op = out + (size_t)b * K * N;
    int k0 = blockIdx.y * 32, n0 = blockIdx.x * 32;
    int tx = threadIdx.x & 31, ty = threadIdx.x >> 5;  // 32x8
#pragma unroll
    for (int i = 0; i < 32; i += 8)
        tile[ty + i][tx] = ip[(size_t)(k0 + ty + i) * N + n0 + tx];
    __syncthreads();
#pragma unroll
    for (int i = 0; i < 32; i += 8) {
        int n = n0 + ty + i;
        int nw = perm ? ((n & 255) * 4 + (n >> 8)) : n;
        op[(size_t)nw * K + k0 + tx] = __float2half_rn(tile[tx][ty + i]);
    }
}

// ---------------- LayerNorm (fp32 input, fp16 output): one warp per token ----------------
__global__ void __launch_bounds__(256) ln_f32(
    const float* __restrict__ x, const float* __restrict__ g,
    const float* __restrict__ b, __half* __restrict__ out, int Mrows)
{
    int warp = (blockIdx.x * blockDim.x + threadIdx.x) >> 5;
    int lane = threadIdx.x & 31;
    if (warp >= Mrows) return;

    const float4* xr = (const float4*)(x + (size_t)warp * EE);
    float4 v[4];
    float s = 0.f, sq = 0.f;
#pragma unroll
    for (int j = 0; j < 4; j++) {
        v[j] = xr[lane + j * 32];
        s  += v[j].x + v[j].y + v[j].z + v[j].w;
        sq += v[j].x*v[j].x + v[j].y*v[j].y + v[j].z*v[j].z + v[j].w*v[j].w;
    }
#pragma unroll
    for (int o = 16; o > 0; o >>= 1) {
        s  += __shfl_xor_sync(0xffffffffu, s, o);
        sq += __shfl_xor_sync(0xffffffffu, sq, o);
    }
    float mean = s * (1.f / EE);
    float var  = sq * (1.f / EE) - mean * mean;
    float rstd = rsqrtf(var + 1e-5f);

    __half2* orow = (__half2*)(out + (size_t)warp * EE);
    const float4* gg4 = (const float4*)g;
    const float4* bb4 = (const float4*)b;
#pragma unroll
    for (int j = 0; j < 4; j++) {
        int e4 = lane + j * 32;
        float4 gg = gg4[e4], bb = bb4[e4];
        float w0 = (v[j].x - mean) * rstd * gg.x + bb.x;
        float w1 = (v[j].y - mean) * rstd * gg.y + bb.y;
        float w2 = (v[j].z - mean) * rstd * gg.z + bb.z;
        float w3 = (v[j].w - mean) * rstd * gg.w + bb.w;
        orow[e4 * 2 + 0] = __floats2half2_rn(w0, w1);
        orow[e4 * 2 + 1] = __floats2half2_rn(w2, w3);
    }
}

// ---------------- LayerNorm (fp16 input, fp16 output) ----------------
__global__ void __launch_bounds__(256) ln_f16(
    const __half* __restrict__ x, const float* __restrict__ g,
    const float* __restrict__ b, __half* __restrict__ out, int Mrows)
{
    int warp = (blockIdx.x * blockDim.x + threadIdx.x) >> 5;
    int lane = threadIdx.x & 31;
    if (warp >= Mrows) return;

    const uint4* xr = (const uint4*)(x + (size_t)warp * EE);  // 8 halves per uint4
    uint4 v[2];
    float f[16];
    float s = 0.f, sq = 0.f;
#pragma unroll
    for (int j = 0; j < 2; j++) {
        v[j] = xr[lane + j * 32];
        const __half2* h2 = (const __half2*)&v[j];
#pragma unroll
        for (int q = 0; q < 4; q++) {
            float2 p = __half22float2(h2[q]);
            f[j * 8 + q * 2 + 0] = p.x;
            f[j * 8 + q * 2 + 1] = p.y;
            s += p.x + p.y;
            sq += p.x * p.x + p.y * p.y;
        }
    }
#pragma unroll
    for (int o = 16; o > 0; o >>= 1) {
        s  += __shfl_xor_sync(0xffffffffu, s, o);
        sq += __shfl_xor_sync(0xffffffffu, sq, o);
    }
    float mean = s * (1.f / EE);
    float var  = sq * (1.f / EE) - mean * mean;
    float rstd = rsqrtf(var + 1e-5f);

    uint4* orow = (uint4*)(out + (size_t)warp * EE);
#pragma unroll
    for (int j = 0; j < 2; j++) {
        int e0 = (lane + j * 32) * 8;
        uint4 w;
        __half2* wh = (__half2*)&w;
#pragma unroll
        for (int q = 0; q < 4; q++) {
            int e = e0 + q * 2;
            float a0 = (f[j * 8 + q * 2 + 0] - mean) * rstd * g[e + 0] + b[e + 0];
            float a1 = (f[j * 8 + q * 2 + 1] - mean) * rstd * g[e + 1] + b[e + 1];
            wh[q] = __floats2half2_rn(a0, a1);
        }
        orow[lane + j * 32] = w;
    }
}

// ---------------- fp16 GEMM: C[M,N] = A[M,512] * Bt[N,512]^T, mma.sync m16n8k16 ----------------
// Tile 128x128x32, 128-thread CTA (2x2 warps, warp tile 64x64), 2 CTAs/SM.
// 4-stage cp.async pipeline + fragment double-buffering; one barrier per chunk.
// SW64-swizzled 64B rows: 16B chunk c stored at c ^ ((row>>1)&3).
#define BM 128
#define BN 128
#define BK 32
#define A_BYT (BM*64)                // 8192
#define B_BYT (BN*64)                // 8192
#define STG_BYT (A_BYT + B_BYT)      // 16384
#define NSTG 4
#define GEMM_SMEM (NSTG*STG_BYT + 128)

__global__ void __launch_bounds__(128, 2) gemm_fp16(
    const __half* __restrict__ A, const __half* __restrict__ Bt,
    const float* __restrict__ bias, __half* __restrict__ C,
    int Mrows, int Ncols, int dlog2, long long dstride)
{
    extern __shared__ __half smh[];
    const uint32_t ub = (su32(smh) + 127u) & ~127u;   // 128B-aligned smem base

    const int tid  = threadIdx.x;
    const int warp = tid >> 5, lane = tid & 31;
    const int g = lane >> 2, t = lane & 3;
    const int wm0 = (warp >> 1) * 64;   // 2 warps along M
    const int wn0 = (warp & 1) * 64;    // 2 warps along N
    const int m0 = blockIdx.y * BM;
    const int n0 = blockIdx.x * BN;
    const int dir = n0 >> dlog2;
    const int ncb = n0 & ((1 << dlog2) - 1);
    const __half* Bbase = Bt + (size_t)dir * dstride + (size_t)ncb * EE;

    // fill coords: row = tid>>2 (+32 per pass), swizzled 16B chunk
    const int frow = tid >> 2;
    const uint32_t fsw16 = (uint32_t)(((tid & 3) ^ ((frow >> 1) & 3)) * 16);
    const int fcol = (tid & 3) * 8;    // source col in halves

    // ldmatrix per-lane swizzled byte offsets (kk=0); kk=16 -> XOR 32
    const int ar = lane & 15;
    const uint32_t a_lane = (uint32_t)(ar * 64 + (((lane >> 4) ^ ((ar >> 1) & 3)) * 16));
    const int br = (lane & 7) | (((lane >> 4) & 1) << 3);
    const uint32_t b_lane = (uint32_t)(br * 64 + ((((lane >> 3) & 1) ^ ((br >> 1) & 3)) * 16));

    float acc[4][8][4];
#pragma unroll
    for (int i = 0; i < 4; i++)
#pragma unroll
        for (int j = 0; j < 8; j++)
#pragma unroll
            for (int k = 0; k < 4; k++) acc[i][j][k] = 0.f;

    auto fill = [&](int kt, int s) {
        uint32_t Ast = ub + s * STG_BYT;
        uint32_t Bst = Ast + A_BYT;
        const int k0 = kt * BK + fcol;
#pragma unroll
        for (int i = 0; i < 4; i++) {
            int r = frow + i * 32;
            int m = m0 + r;
            bool ok = (m < Mrows);
            cp16(Ast + (uint32_t)(r * 64) + fsw16,
                 A + (size_t)(ok ? m : 0) * EE + k0, ok ? 16 : 0);
        }
#pragma unroll
        for (int i = 0; i < 4; i++) {
            int r = frow + i * 32;
            cp16(Bst + (uint32_t)(r * 64) + fsw16, Bbase + (size_t)r * EE + k0, 16);
        }
    };

    // fragment double buffers
    uint32_t afA[4][4], bfA[8][2], afB[4][4], bfB[8][2];

    auto ldsm_frags = [&](int s, int ks, uint32_t af[4][4], uint32_t bf[8][2]) {
        const uint32_t kx = ks ? 32u : 0u;
        const uint32_t a_base = ub + s * STG_BYT + a_lane;
        const uint32_t b_base = ub + s * STG_BYT + A_BYT + b_lane;
#pragma unroll
        for (int i = 0; i < 4; i++)
            ldsm4(af[i][0], af[i][1], af[i][2], af[i][3],
                  (a_base + (uint32_t)((wm0 + i * 16) * 64)) ^ kx);
#pragma unroll
        for (int jp = 0; jp < 4; jp++) {
            int j = jp * 2;
            ldsm4(bf[j][0], bf[j][1], bf[j + 1][0], bf[j + 1][1],
                  (b_base + (uint32_t)((wn0 + j * 8) * 64)) ^ kx);
        }
    };

    auto do_mma = [&](uint32_t af[4][4], uint32_t bf[8][2]) {
#pragma unroll
        for (int i = 0; i < 4; i++)
#pragma unroll
            for (int j = 0; j < 8; j++)
                mma_f16(acc[i][j], af[i], bf[j]);
    };

    const int NKT = EE / BK;  // 16

    fill(0, 0); asm volatile("cp.async.commit_group;");
    fill(1, 1); asm volatile("cp.async.commit_group;");
    fill(2, 2); asm volatile("cp.async.commit_group;");
    asm volatile("cp.async.wait_group 2;");
    __syncthreads();
    ldsm_frags(0, 0, afA, bfA);

    for (int c = 0; c < NKT; c++) {
        const int s = c & 3;
        ldsm_frags(s, 1, afB, bfB);       // overlaps mma below
        do_mma(afA, bfA);
        asm volatile("cp.async.wait_group 1;");  // stage c+1 groups complete
        __syncthreads();                         // visibility + safe overwrite of stage c-1
        if (c + 3 < NKT) fill(c + 3, (c + 3) & 3);
        asm volatile("cp.async.commit_group;");
        if (c + 1 < NKT) ldsm_frags((c + 1) & 3, 0, afA, bfA);  // overlaps mma below
        do_mma(afB, bfB);
    }

    // epilogue: fp32 acc (+bias) -> fp16 stores
#pragma unroll
    for (int i = 0; i < 4; i++) {
        int r0 = m0 + wm0 + i * 16 + g;
        int r1 = r0 + 8;
#pragma unroll
        for (int j = 0; j < 8; j++) {
            int cc = n0 + wn0 + j * 8 + 2 * t;
            float b0v = 0.f, b1v = 0.f;
            if (bias) { b0v = bias[cc]; b1v = bias[cc + 1]; }
            if (r0 < Mrows)
                *(__half2*)(C + (size_t)r0 * Ncols + cc) =
                    __floats2half2_rn(acc[i][j][0] + b0v, acc[i][j][1] + b1v);
            if (r1 < Mrows)
                *(__half2*)(C + (size_t)r1 * Ncols + cc) =
                    __floats2half2_rn(acc[i][j][2] + b0v, acc[i][j][3] + b1v);
        }
    }
}

// ---------------- SRU elementwise scan: gate-interleaved U (uint2 per step) ----------------
__global__ void __launch_bounds__(256) sru_scan(
    const __half* __restrict__ U, const float* __restrict__ v,
    const float* __restrict__ bp, __half* __restrict__ X)
{
    int tid = blockIdx.x * blockDim.x + threadIdx.x;
    if (tid >= 2 * BB * DD) return;
    int dir = tid / (BB * DD);
    int rem = tid - dir * (BB * DD);
    int b = rem / DD;
    int dd = rem - b * DD;

    float vf = v[dir * 2 * DD + dd];
    float vr = v[dir * 2 * DD + DD + dd];
    float bf = bp[dir * 2 * DD + dd];
    float br = bp[dir * 2 * DD + DD + dd];

    const size_t colU = (size_t)dir * 1024 + (size_t)dd * 4;  // gate-interleaved
    const size_t colX = (size_t)dir * DD + dd;

    float c = 0.f;
    for (int s = 0; s < TT; s++) {
        int t = dir ? (TT - 1 - s) : s;
        const __half* up = U + ((size_t)t * BB + b) * 2048 + colU;
        uint2 raw = *(const uint2*)up;            // u0,u1,u2,u3
        float2 p0 = __half22float2(*(const __half2*)&raw.x);
        float2 p1 = __half22float2(*(const __half2*)&raw.y);
        float u0 = p0.x, u1 = p0.y, u2 = p1.x, u3 = p1.y;
        float f = 1.f / (1.f + expf(-(u1 + vf * c + bf)));
        c = f * c + (1.f - f) * u0;
        float r = 1.f / (1.f + expf(-(u2 + vr * c + br)));
        X[((size_t)t * BB + b) * EE + colX] = __float2half_rn(r * c + (1.f - r) * u3);
    }
}

// ---------------- head: BN(eval) + relu + W2 (512x4) + log_softmax; one warp per token ----------------
__global__ void __launch_bounds__(256) head_kernel(
    const __half* __restrict__ h,
    const float* __restrict__ bn_g, const float* __restrict__ bn_b,
    const float* __restrict__ bn_mean, const float* __restrict__ bn_var,
    const float* __restrict__ W2, const float* __restrict__ b2,
    float* __restrict__ out, int Mrows)
{
    __shared__ float w2s[EE * 4];
    __shared__ float scs[EE], tbs[EE];
    __shared__ float b2s[4];
    int tid = threadIdx.x;
    for (int i = tid; i < EE * 4; i += 256) w2s[i] = W2[i];
    for (int i = tid; i < EE; i += 256) {
        float s = bn_g[i] * rsqrtf(bn_var[i] + 1e-5f);
        scs[i] = s;
        tbs[i] = bn_b[i] - bn_mean[i] * s;
    }
    if (tid < 4) b2s[tid] = b2[tid];
    __syncthreads();

    int warp = (blockIdx.x * blockDim.x + tid) >> 5;
    int lane = tid & 31;
    if (warp >= Mrows) return;

    const uint4* hr = (const uint4*)(h + (size_t)warp * EE);  // 8 halves per uint4
    float a0 = 0.f, a1 = 0.f, a2 = 0.f, a3 = 0.f;
#pragma unroll
    for (int j = 0; j < 2; j++) {
        uint4 hv = hr[lane + j * 32];
        const __half2* h2 = (const __half2*)&hv;
        int e0 = (lane + j * 32) * 8;
#pragma unroll
        for (int q = 0; q < 4; q++) {
            float2 p = __half22float2(h2[q]);
            int e = e0 + q * 2;
            float v0 = fmaxf(p.x * scs[e]     + tbs[e],     0.f);
            float v1 = fmaxf(p.y * scs[e + 1] + tbs[e + 1], 0.f);
            a0 += v0 * w2s[e * 4 + 0] + v1 * w2s[(e + 1) * 4 + 0];
            a1 += v0 * w2s[e * 4 + 1] + v1 * w2s[(e + 1) * 4 + 1];
            a2 += v0 * w2s[e * 4 + 2] + v1 * w2s[(e + 1) * 4 + 2];
            a3 += v0 * w2s[e * 4 + 3] + v1 * w2s[(e + 1) * 4 + 3];
        }
    }
#pragma unroll
    for (int o = 16; o > 0; o >>= 1) {
        a0 += __shfl_xor_sync(0xffffffffu, a0, o);
        a1 += __shfl_xor_sync(0xffffffffu, a1, o);
        a2 += __shfl_xor_sync(0xffffffffu, a2, o);
        a3 += __shfl_xor_sync(0xffffffffu, a3, o);
    }
    if (lane == 0) {
        float l0 = a0 + b2s[0], l1 = a1 + b2s[1], l2 = a2 + b2s[2], l3 = a3 + b2s[3];
        float m = fmaxf(fmaxf(l0, l1), fmaxf(l2, l3));
        float se = expf(l0 - m) + expf(l1 - m) + expf(l2 - m) + expf(l3 - m);
        float lse = m + logf(se);
        float4 o = make_float4(l0 - lse, l1 - lse, l2 - lse, l3 - lse);
        ((float4*)out)[warp] = o;
    }
}

// ---------------- launch ----------------
extern "C" void kernel_launch(void* const* d_in, const int* in_sizes, int n_in,
                              void* d_out, int out_size)
{
    const float* sentence = (const float*)d_in[0];
    const float* sru_W    = (const float*)d_in[1];
    const float* sru_v    = (const float*)d_in[2];
    const float* sru_b    = (const float*)d_in[3];
    const float* ln_g     = (const float*)d_in[4];
    const float* ln_b     = (const float*)d_in[5];
    const float* W1       = (const float*)d_in[6];
    const float* b1       = (const float*)d_in[7];
    const float* bn_g     = (const float*)d_in[8];
    const float* bn_b     = (const float*)d_in[9];
    const float* bn_mean  = (const float*)d_in[10];
    const float* bn_var   = (const float*)d_in[11];
    const float* W2       = (const float*)d_in[12];
    const float* b2       = (const float*)d_in[13];
    float* out = (float*)d_out;

    __half *xl, *U, *x, *Wr, *W1r;
    cudaGetSymbolAddress((void**)&xl,  g_xl);
    cudaGetSymbolAddress((void**)&U,   g_U);
    cudaGetSymbolAddress((void**)&x,   g_x);
    cudaGetSymbolAddress((void**)&Wr,  g_Wr);
    cudaGetSymbolAddress((void**)&W1r, g_W1r);

    cudaFuncSetAttribute(gemm_fp16, cudaFuncAttributeMaxDynamicSharedMemorySize, GEMM_SMEM);

    const int M = MROWS;
    const int mtiles = (M + BM - 1) / BM;        // 782
    dim3 gemm_grid_layer(2048 / BN, mtiles);     // (16, 782)
    dim3 gemm_grid_head(EE / BN, mtiles);        // (4, 782)
    int ln_blocks = (M * 32 + 255) / 256;        // 12500
    int scan_blocks = (2 * BB * DD + 255) / 256; // 2000

    // transpose + fp16-round weights (sru_W gate-interleaved; W1 plain)
    transpose_half<<<dim3(1024 / 32, EE / 32, LL * 2), 256>>>(sru_W, Wr, EE, 1024, 1);
    transpose_half<<<dim3(EE / 32, EE / 32, 1), 256>>>(W1, W1r, EE, EE, 0);

    for (int l = 0; l < LL; l++) {
        if (l == 0)
            ln_f32<<<ln_blocks, 256>>>(sentence, ln_g, ln_b, xl, M);
        else
            ln_f16<<<ln_blocks, 256>>>(x, ln_g + l * EE, ln_b + l * EE, xl, M);
        gemm_fp16<<<gemm_grid_layer, 128, GEMM_SMEM>>>(
            xl, Wr + (size_t)l * 2 * 1024 * EE, nullptr, U,
            M, 2048, 10, (long long)1024 * EE);
        sru_scan<<<scan_blocks, 256>>>(U, sru_v + l * 4 * DD, sru_b + l * 4 * DD, x);
    }
    // head GEMM: h = x @ W1 + b1 -> xl
    gemm_fp16<<<gemm_grid_head, 128, GEMM_SMEM>>>(
        x, W1r, b1, xl, M, EE, 30, 0LL);
    head_kernel<<<ln_blocks, 256>>>(xl, bn_g, bn_b, bn_mean, bn_var, W2, b2, out, M);
}